// round 4
// baseline (speedup 1.0000x reference)
#include <cuda_runtime.h>
#include <cstdint>

// ---------------- problem constants ----------------
#define T_TOK   32768            // B*S tokens
#define NXD     1024             // feature dim
#define A_CNT   20               // adapters
#define H_CNT   50               // hidden
#define O_CNT   3                // outputs per adapter
#define NC      1000             // A_CNT*H_CNT flat columns
#define S_LEN   2048
#define LN_EPS  1e-5f

// ---------------- device scratch (sanctioned __device__ globals) ----------------
__device__ float g_mu[T_TOK];
__device__ float g_rstd[T_TOK];
__device__ float g_off[NC];
__device__ float g_hbuf[(size_t)T_TOK * NC];   // 131 MB relu(xn@W1g + off)

// =====================================================================
// K1: per-token LayerNorm statistics (mean, rstd). One block per token.
// =====================================================================
__global__ void __launch_bounds__(256) k_lnstats(const float* __restrict__ x) {
    const int t = blockIdx.x;
    const float4* xv = reinterpret_cast<const float4*>(x) + (size_t)t * 256;
    float4 v = xv[threadIdx.x];
    float s  = v.x + v.y + v.z + v.w;
    float q  = v.x * v.x + v.y * v.y + v.z * v.z + v.w * v.w;
    #pragma unroll
    for (int o = 16; o > 0; o >>= 1) {
        s += __shfl_xor_sync(0xffffffffu, s, o);
        q += __shfl_xor_sync(0xffffffffu, q, o);
    }
    __shared__ float ss[8], qq[8];
    const int w = threadIdx.x >> 5;
    if ((threadIdx.x & 31) == 0) { ss[w] = s; qq[w] = q; }
    __syncthreads();
    if (threadIdx.x == 0) {
        float S = 0.f, Q = 0.f;
        #pragma unroll
        for (int i = 0; i < 8; i++) { S += ss[i]; Q += qq[i]; }
        float mu  = S * (1.0f / (float)NXD);
        float var = Q * (1.0f / (float)NXD) - mu * mu;
        var = fmaxf(var, 0.0f);
        g_mu[t]   = mu;
        g_rstd[t] = 1.0f / sqrtf(var + LN_EPS);
    }
}

// =====================================================================
// K2: off[a,h] = sum_n ln_b[a,n]*W1[a,n,h] + b1[a,h]   (beta folding)
// grid = A_CNT blocks of 64 threads (50 active)
// =====================================================================
__global__ void __launch_bounds__(64) k_off(const float* __restrict__ ln_b,
                                            const float* __restrict__ W1,
                                            const float* __restrict__ b1) {
    const int a = blockIdx.x;
    const int h = threadIdx.x;
    if (h >= H_CNT) return;
    const float* lb = ln_b + a * NXD;
    const float* w  = W1 + (size_t)a * NXD * H_CNT + h;
    float acc = 0.0f;
    #pragma unroll 8
    for (int n = 0; n < NXD; n++) acc += lb[n] * w[(size_t)n * H_CNT];
    g_off[a * H_CNT + h] = acc + b1[a * H_CNT + h];
}

// =====================================================================
// K3: main GEMM  H = relu( xn @ (ln_g ⊙ W1) + off )
//   M = 32768 tokens, N = 1024 (cols 1000..1023 wasted), K = 1024
//   BM=128, BN=128, BK=8; 256 threads; micro-tile 8(M) x 8(N)
//   Accumulators are f32x2 pairs along N; A is stored DUPLICATED {a,a}
//   in smem so the inner loop is pure fma.rn.f32x2 (FFMA2).
//   LN normalization folded into A load; gamma folded into B load.
// =====================================================================
__global__ void __launch_bounds__(256, 2) k_gemm(const float* __restrict__ x,
                                                 const float* __restrict__ ln_g,
                                                 const float* __restrict__ W1) {
    __shared__ float2 As[8][128];   // duplicated A: As[k][m] = {a,a}
    __shared__ float  Bs[8][128];

    const int tid = threadIdx.x;
    const int tx  = tid & 15;       // N direction (8 cols each)
    const int ty  = tid >> 4;       // M direction (8 rows each)
    const int nt  = blockIdx.x;     // 0..7
    const int mt  = blockIdx.y;     // 0..255

    // ---- A-tile load mapping: thread owns one token row, half the k-chunk
    const int am  = tid >> 1;       // 0..127 row within tile
    const int ak4 = tid & 1;        // which float4 of the 8-wide k chunk
    const int tok = mt * 128 + am;
    const float mu = g_mu[tok];
    const float rs = g_rstd[tok];
    const float4* xrow = reinterpret_cast<const float4*>(x) + (size_t)tok * 256;

    // ---- B-tile load mapping: 8 k-rows x 128 cols, 4 cols per thread
    const int bk = tid >> 5;            // 0..7
    const int bc = (tid & 31) * 4;      // 0..124
    int  aidx[4], wbase[4];
    bool cval[4];
    #pragma unroll
    for (int q = 0; q < 4; q++) {
        int ci = nt * 128 + bc + q;
        cval[q] = (ci < NC);
        int a = ci / H_CNT;
        if (!cval[q]) a = 0;            // keep speculative loads in-bounds
        int h = ci - a * H_CNT;
        aidx[q]  = a;
        wbase[q] = a * (NXD * H_CNT) + h;
    }

    unsigned long long acc[8][4];
    #pragma unroll
    for (int m = 0; m < 8; m++)
        #pragma unroll
        for (int p = 0; p < 4; p++) acc[m][p] = 0ull;

    // ---- prologue: prefetch tile kt=0 into registers
    float4 areg = xrow[ak4];
    float  breg[4];
    {
        const int n = bk;
        #pragma unroll
        for (int q = 0; q < 4; q++)
            breg[q] = cval[q] ? ln_g[aidx[q] * NXD + n] * W1[wbase[q] + n * H_CNT] : 0.0f;
    }

    for (int kt = 0; kt < 128; kt++) {
        // commit prefetched tile to smem (normalize A, duplicate it)
        {
            float vv[4] = {areg.x, areg.y, areg.z, areg.w};
            #pragma unroll
            for (int i = 0; i < 4; i++) {
                float nv = (vv[i] - mu) * rs;
                As[ak4 * 4 + i][am] = make_float2(nv, nv);
            }
            *reinterpret_cast<float4*>(&Bs[bk][bc]) =
                make_float4(breg[0], breg[1], breg[2], breg[3]);
        }
        __syncthreads();

        // prefetch next tile while computing current one
        if (kt < 127) {
            areg = xrow[(kt + 1) * 2 + ak4];
            const int n = (kt + 1) * 8 + bk;
            #pragma unroll
            for (int q = 0; q < 4; q++)
                breg[q] = cval[q] ? ln_g[aidx[q] * NXD + n] * W1[wbase[q] + n * H_CNT] : 0.0f;
        }

        // ---- inner product: 8 k-steps, 8x4 FFMA2 each (= 64 FMA/thread/k)
        #pragma unroll
        for (int k = 0; k < 8; k++) {
            unsigned long long a_[8], b_[4];
            const ulonglong2* ap = reinterpret_cast<const ulonglong2*>(&As[k][ty * 8]);
            ulonglong2 t0 = ap[0], t1 = ap[1], t2 = ap[2], t3 = ap[3];
            a_[0] = t0.x; a_[1] = t0.y; a_[2] = t1.x; a_[3] = t1.y;
            a_[4] = t2.x; a_[5] = t2.y; a_[6] = t3.x; a_[7] = t3.y;
            const ulonglong2* bp = reinterpret_cast<const ulonglong2*>(&Bs[k][tx * 8]);
            ulonglong2 u0 = bp[0], u1 = bp[1];
            b_[0] = u0.x; b_[1] = u0.y; b_[2] = u1.x; b_[3] = u1.y;
            #pragma unroll
            for (int m = 0; m < 8; m++)
                #pragma unroll
                for (int p = 0; p < 4; p++)
                    asm("fma.rn.f32x2 %0, %1, %2, %0;"
                        : "+l"(acc[m][p]) : "l"(a_[m]), "l"(b_[p]));
        }
        __syncthreads();
    }

    // ---- epilogue: +off, relu, store to g_hbuf (row length NC=1000)
    #pragma unroll
    for (int m = 0; m < 8; m++) {
        const int row = mt * 128 + ty * 8 + m;
        float* hb = g_hbuf + (size_t)row * NC;
        #pragma unroll
        for (int p = 0; p < 4; p++) {
            const int c0 = nt * 128 + tx * 8 + p * 2;
            float lo = __uint_as_float((unsigned)(acc[m][p] & 0xffffffffull));
            float hi = __uint_as_float((unsigned)(acc[m][p] >> 32));
            if (c0 < NC)     hb[c0]     = fmaxf(lo + g_off[c0], 0.0f);
            if (c0 + 1 < NC) hb[c0 + 1] = fmaxf(hi + g_off[c0 + 1], 0.0f);
        }
    }
}

// =====================================================================
// K4: per-token second GEMM (50->3 per adapter) + cross-adapter squash
//   o[a,j] = h·W2[a,:,j] + b2 ;  sq[j] = sum_a o^2 ; out = o*sqrt(sq)/(1+sq)
//   One warp per token, 8 tokens per block.
// =====================================================================
__global__ void __launch_bounds__(256) k_out(const float* __restrict__ W2,
                                             const float* __restrict__ b2,
                                             float* __restrict__ out) {
    __shared__ float W2s[A_CNT * H_CNT * O_CNT];  // 3000
    __shared__ float b2s[A_CNT * O_CNT];          // 60
    __shared__ float hrow[8][NC];
    __shared__ float osm[8][64];
    __shared__ float scl[8][4];

    const int tid = threadIdx.x;
    for (int i = tid; i < A_CNT * H_CNT * O_CNT; i += 256) W2s[i] = W2[i];
    if (tid < A_CNT * O_CNT) b2s[tid] = b2[tid];
    __syncthreads();

    const int w = tid >> 5, l = tid & 31;
    const int t = blockIdx.x * 8 + w;
    const float* hb = g_hbuf + (size_t)t * NC;
    #pragma unroll
    for (int i = 0; i < 32; i++) {
        int idx = i * 32 + l;
        if (idx < NC) hrow[w][idx] = hb[idx];
    }
    __syncwarp();

    #pragma unroll
    for (int r = 0; r < 2; r++) {
        const int p = l + r * 32;
        if (p < A_CNT * O_CNT) {
            const int a = p / 3, j = p - a * 3;
            const float* hr = &hrow[w][a * H_CNT];
            const float* w2 = &W2s[a * H_CNT * O_CNT + j];
            float o = b2s[p];
            #pragma unroll
            for (int h = 0; h < H_CNT; h++) o += hr[h] * w2[h * 3];
            osm[w][p] = o;
        }
    }
    __syncwarp();

    if (l < O_CNT) {
        float sq = 0.0f;
        #pragma unroll
        for (int a = 0; a < A_CNT; a++) { float v = osm[w][a * 3 + l]; sq += v * v; }
        scl[w][l] = sqrtf(sq) / (1.0f + sq);   // == (sq/(1+sq)) * rsqrt(sq)
    }
    __syncwarp();

    const int b = t >> 11, sidx = t & (S_LEN - 1);
    #pragma unroll
    for (int r = 0; r < 2; r++) {
        const int p = l + r * 32;
        if (p < A_CNT * O_CNT) {
            const int a = p / 3, j = p - a * 3;
            out[(size_t)(b * A_CNT + a) * (S_LEN * O_CNT) + sidx * 3 + j] =
                osm[w][p] * scl[w][j];
        }
    }
}

// =====================================================================
// launch
// =====================================================================
extern "C" void kernel_launch(void* const* d_in, const int* in_sizes, int n_in,
                              void* d_out, int out_size) {
    (void)in_sizes; (void)n_in; (void)out_size;
    const float* x    = (const float*)d_in[0];
    const float* ln_g = (const float*)d_in[1];
    const float* ln_b = (const float*)d_in[2];
    const float* W1   = (const float*)d_in[3];
    const float* b1   = (const float*)d_in[4];
    const float* W2   = (const float*)d_in[5];
    const float* b2   = (const float*)d_in[6];
    float* out = (float*)d_out;

    k_lnstats<<<T_TOK, 256>>>(x);
    k_off<<<A_CNT, 64>>>(ln_b, W1, b1);
    k_gemm<<<dim3(8, 256), 256>>>(x, ln_g, W1);
    k_out<<<T_TOK / 8, 256>>>(W2, b2, out);
}

// round 6
// speedup vs baseline: 2.6295x; 2.6295x over previous
#include <cuda_runtime.h>
#include <cuda_bf16.h>
#include <cstdint>

// ---------------- problem constants ----------------
#define T_TOK   32768            // B*S tokens
#define NXD     1024             // feature dim (K)
#define A_CNT   20
#define H_CNT   50
#define O_CNT   3
#define NC      1000             // A_CNT*H_CNT real columns
#define NPAD    1024             // padded N
#define S_LEN   2048
#define LN_EPS  1e-5f

// ---------------- device scratch ----------------
__device__ float g_off[NC];
__device__ float g_hbuf[(size_t)T_TOK * NC];                       // 131 MB
__device__ __align__(16) __nv_bfloat16 g_Ahi[(size_t)T_TOK * NXD]; // 64 MB
__device__ __align__(16) __nv_bfloat16 g_Alo[(size_t)T_TOK * NXD]; // 64 MB
__device__ __align__(16) __nv_bfloat16 g_Bhi[(size_t)NPAD * NXD];  // 2 MB
__device__ __align__(16) __nv_bfloat16 g_Blo[(size_t)NPAD * NXD];  // 2 MB

__device__ __forceinline__ uint32_t s2u(const void* p) {
    uint32_t a;
    asm("{ .reg .u64 t; cvta.to.shared.u64 t, %1; cvt.u32.u64 %0, t; }"
        : "=r"(a) : "l"(p));
    return a;
}
__device__ __forceinline__ unsigned pk2(__nv_bfloat16 a, __nv_bfloat16 b) {
    return (unsigned)__bfloat16_as_ushort(a) | ((unsigned)__bfloat16_as_ushort(b) << 16);
}

#define CP16(saddr, gaddr) \
    asm volatile("cp.async.cg.shared.global [%0], [%1], 16;" :: "r"(saddr), "l"(gaddr))
#define CP_COMMIT() asm volatile("cp.async.commit_group;" ::: "memory")
#define CP_WAIT0()  asm volatile("cp.async.wait_group 0;" ::: "memory")

#define LDSM4(r, addr) \
    asm volatile("ldmatrix.sync.aligned.m8n8.x4.shared.b16 {%0,%1,%2,%3}, [%4];" \
        : "=r"((r)[0]), "=r"((r)[1]), "=r"((r)[2]), "=r"((r)[3]) : "r"(addr))

#define MMA16816(d, a, b0, b1) \
    asm volatile("mma.sync.aligned.m16n8k16.row.col.f32.bf16.bf16.f32 " \
        "{%0,%1,%2,%3}, {%4,%5,%6,%7}, {%8,%9}, {%0,%1,%2,%3};" \
        : "+f"((d)[0]), "+f"((d)[1]), "+f"((d)[2]), "+f"((d)[3]) \
        : "r"((a)[0]), "r"((a)[1]), "r"((a)[2]), "r"((a)[3]), "r"(b0), "r"(b1))

// =====================================================================
// K1: per-token LN stats + bf16 hi/lo split of xn (fused)
// =====================================================================
__global__ void __launch_bounds__(256) k_split(const float* __restrict__ x) {
    const int t = blockIdx.x;
    const float4 v = reinterpret_cast<const float4*>(x)[(size_t)t * 256 + threadIdx.x];
    float s = v.x + v.y + v.z + v.w;
    float q = v.x * v.x + v.y * v.y + v.z * v.z + v.w * v.w;
    #pragma unroll
    for (int o = 16; o > 0; o >>= 1) {
        s += __shfl_xor_sync(0xffffffffu, s, o);
        q += __shfl_xor_sync(0xffffffffu, q, o);
    }
    __shared__ float ss[8], qq[8], smu, srs;
    const int w = threadIdx.x >> 5;
    if ((threadIdx.x & 31) == 0) { ss[w] = s; qq[w] = q; }
    __syncthreads();
    if (threadIdx.x == 0) {
        float S = 0.f, Q = 0.f;
        #pragma unroll
        for (int i = 0; i < 8; i++) { S += ss[i]; Q += qq[i]; }
        float mu  = S * (1.0f / (float)NXD);
        float var = fmaxf(Q * (1.0f / (float)NXD) - mu * mu, 0.0f);
        smu = mu;
        srs = 1.0f / sqrtf(var + LN_EPS);
    }
    __syncthreads();
    const float mu = smu, rs = srs;
    float n0 = (v.x - mu) * rs, n1 = (v.y - mu) * rs;
    float n2 = (v.z - mu) * rs, n3 = (v.w - mu) * rs;
    __nv_bfloat16 h0 = __float2bfloat16(n0), h1 = __float2bfloat16(n1);
    __nv_bfloat16 h2 = __float2bfloat16(n2), h3 = __float2bfloat16(n3);
    __nv_bfloat16 l0 = __float2bfloat16(n0 - __bfloat162float(h0));
    __nv_bfloat16 l1 = __float2bfloat16(n1 - __bfloat162float(h1));
    __nv_bfloat16 l2 = __float2bfloat16(n2 - __bfloat162float(h2));
    __nv_bfloat16 l3 = __float2bfloat16(n3 - __bfloat162float(h3));
    uint2 H, L;
    H.x = pk2(h0, h1); H.y = pk2(h2, h3);
    L.x = pk2(l0, l1); L.y = pk2(l2, l3);
    reinterpret_cast<uint2*>(g_Ahi)[(size_t)t * 256 + threadIdx.x] = H;
    reinterpret_cast<uint2*>(g_Alo)[(size_t)t * 256 + threadIdx.x] = L;
}

// =====================================================================
// K2a: B = (ln_g ⊙ W1)^T -> [NPAD][K] bf16 hi/lo (pad rows zero)
// =====================================================================
__global__ void __launch_bounds__(256) k_prepB(const float* __restrict__ ln_g,
                                               const float* __restrict__ W1) {
    const int n = blockIdx.x;
    int a = 0, h = 0;
    const bool val = (n < NC);
    if (val) { a = n / H_CNT; h = n - a * H_CNT; }
    #pragma unroll
    for (int j = 0; j < 4; j++) {
        const int k = threadIdx.x + j * 256;
        float wv = val ? ln_g[a * NXD + k] * W1[((size_t)a * NXD + k) * H_CNT + h] : 0.0f;
        __nv_bfloat16 hi = __float2bfloat16(wv);
        __nv_bfloat16 lo = __float2bfloat16(wv - __bfloat162float(hi));
        g_Bhi[(size_t)n * NXD + k] = hi;
        g_Blo[(size_t)n * NXD + k] = lo;
    }
}

// =====================================================================
// K2b: off[a,h] = ln_b[a,:]·W1[a,:,h] + b1[a,h]
// =====================================================================
__global__ void __launch_bounds__(64) k_off(const float* __restrict__ ln_b,
                                            const float* __restrict__ W1,
                                            const float* __restrict__ b1) {
    const int a = blockIdx.x;
    const int h = threadIdx.x;
    if (h >= H_CNT) return;
    const float* lb = ln_b + a * NXD;
    const float* w  = W1 + (size_t)a * NXD * H_CNT + h;
    float acc = 0.0f;
    #pragma unroll 8
    for (int n = 0; n < NXD; n++) acc += lb[n] * w[(size_t)n * H_CNT];
    g_off[a * H_CNT + h] = acc + b1[a * H_CNT + h];
}

// =====================================================================
// K3: mma.sync bf16 split GEMM  hbuf = relu(xn @ W1g + off)
//   CTA 128x128, BK=64, 8 warps (warp tile 32x64), cp.async 2-stage.
//   smem tile: 128 rows x 144B (128B data + 16B pad -> ldmatrix conflict-free)
//   Stage = Ahi|Alo|Bhi|Blo = 4 x 18432 B = 73728 B; 2 stages = 147456 B.
// =====================================================================
#define SSTR   144
#define TILE_B (128 * SSTR)          // 18432
#define STAGE  (4 * TILE_B)          // 73728
#define SMEMT  (2 * STAGE)           // 147456

__global__ void __launch_bounds__(256, 1) k_gemm() {
    extern __shared__ __align__(16) char smem[];
    const uint32_t sb = s2u(smem);
    const int tid = threadIdx.x;
    const int w = tid >> 5, l = tid & 31;
    const int wm = w & 3, wn = w >> 2;          // 4 x 2 warp grid
    const int bx = blockIdx.x;                  // N tile 0..7 (fastest -> A reuse in L2)
    const int by = blockIdx.y;                  // M tile 0..255

    // ---- loader mapping: 4 chunks of 16B per tile per thread ----
    // chunk c = tid + i*256 : row = c>>3, kq = c&7
    unsigned lrow[4], lkq[4], soff[4];
    #pragma unroll
    for (int i = 0; i < 4; i++) {
        unsigned c = tid + i * 256;
        lrow[i] = c >> 3;
        lkq[i]  = c & 7;
        soff[i] = lrow[i] * SSTR + lkq[i] * 16;
    }
    const char* gAh = reinterpret_cast<const char*>(g_Ahi);
    const char* gAl = reinterpret_cast<const char*>(g_Alo);
    const char* gBh = reinterpret_cast<const char*>(g_Bhi);
    const char* gBl = reinterpret_cast<const char*>(g_Blo);

    // issue one stage of loads (kt -> stage s)
    auto load_stage = [&](int kt, int s) {
        const uint32_t st = sb + s * STAGE;
        #pragma unroll
        for (int i = 0; i < 4; i++) {
            size_t ga = ((size_t)(by * 128 + lrow[i]) * NXD + kt * 64 + lkq[i] * 8) * 2;
            CP16(st + soff[i],              gAh + ga);
            CP16(st + TILE_B + soff[i],     gAl + ga);
            size_t gb = ((size_t)(bx * 128 + lrow[i]) * NXD + kt * 64 + lkq[i] * 8) * 2;
            CP16(st + 2 * TILE_B + soff[i], gBh + gb);
            CP16(st + 3 * TILE_B + soff[i], gBl + gb);
        }
        CP_COMMIT();
    };

    // ---- ldmatrix base addresses (per lane) ----
    uint32_t abase[2], bbase[4];
    #pragma unroll
    for (int mi = 0; mi < 2; mi++)
        abase[mi] = (wm * 32 + mi * 16 + (l & 15)) * SSTR + (l >> 4) * 16;
    #pragma unroll
    for (int pi = 0; pi < 4; pi++)
        bbase[pi] = (wn * 64 + pi * 16 + (l & 15)) * SSTR + (l >> 4) * 16;

    float acc[2][8][4];
    #pragma unroll
    for (int mi = 0; mi < 2; mi++)
        #pragma unroll
        for (int ni = 0; ni < 8; ni++)
            #pragma unroll
            for (int r = 0; r < 4; r++) acc[mi][ni][r] = 0.0f;

    load_stage(0, 0);

    for (int kt = 0; kt < 16; kt++) {
        const int s = kt & 1;
        CP_WAIT0();
        __syncthreads();
        if (kt < 15) load_stage(kt + 1, s ^ 1);

        const uint32_t stA = sb + s * STAGE;
        const uint32_t stB = stA + 2 * TILE_B;
        #pragma unroll
        for (int ks = 0; ks < 4; ks++) {
            const uint32_t ko = ks * 32;
            uint32_t ah[2][4], al[2][4], bh[4][4], bl[4][4];
            #pragma unroll
            for (int mi = 0; mi < 2; mi++) {
                LDSM4(ah[mi], stA + abase[mi] + ko);
                LDSM4(al[mi], stA + TILE_B + abase[mi] + ko);
            }
            #pragma unroll
            for (int pi = 0; pi < 4; pi++) {
                LDSM4(bh[pi], stB + bbase[pi] + ko);
                LDSM4(bl[pi], stB + TILE_B + bbase[pi] + ko);
            }
            #pragma unroll
            for (int mi = 0; mi < 2; mi++)
                #pragma unroll
                for (int ni = 0; ni < 8; ni++) {
                    const int pi = ni >> 1, sel = ni & 1;
                    MMA16816(acc[mi][ni], ah[mi], bh[pi][sel], bh[pi][sel + 2]);
                    MMA16816(acc[mi][ni], ah[mi], bl[pi][sel], bl[pi][sel + 2]);
                    MMA16816(acc[mi][ni], al[mi], bh[pi][sel], bh[pi][sel + 2]);
                }
        }
        __syncthreads();
    }

    // ---- epilogue: +off, relu, STG.64 to g_hbuf ----
    const int r0  = by * 128 + wm * 32 + (l >> 2);
    const int cb0 = bx * 128 + wn * 64 + (l & 3) * 2;
    #pragma unroll
    for (int mi = 0; mi < 2; mi++) {
        #pragma unroll
        for (int ni = 0; ni < 8; ni++) {
            const int gc = cb0 + ni * 8;
            if (gc < NC) {   // gc even, NC even -> gc+1 also valid
                const float o0 = g_off[gc], o1 = g_off[gc + 1];
                float* hb0 = g_hbuf + (size_t)(r0 + mi * 16) * NC + gc;
                float* hb1 = hb0 + (size_t)8 * NC;
                float2 v0, v1;
                v0.x = fmaxf(acc[mi][ni][0] + o0, 0.0f);
                v0.y = fmaxf(acc[mi][ni][1] + o1, 0.0f);
                v1.x = fmaxf(acc[mi][ni][2] + o0, 0.0f);
                v1.y = fmaxf(acc[mi][ni][3] + o1, 0.0f);
                *reinterpret_cast<float2*>(hb0) = v0;
                *reinterpret_cast<float2*>(hb1) = v1;
            }
        }
    }
}

// =====================================================================
// K4: per-token 50->3 GEMM per adapter + cross-adapter squash
// =====================================================================
__global__ void __launch_bounds__(256) k_out(const float* __restrict__ W2,
                                             const float* __restrict__ b2,
                                             float* __restrict__ out) {
    __shared__ float W2s[A_CNT * H_CNT * O_CNT];
    __shared__ float b2s[A_CNT * O_CNT];
    __shared__ float hrow[8][NC];
    __shared__ float osm[8][64];
    __shared__ float scl[8][4];

    const int tid = threadIdx.x;
    for (int i = tid; i < A_CNT * H_CNT * O_CNT; i += 256) W2s[i] = W2[i];
    if (tid < A_CNT * O_CNT) b2s[tid] = b2[tid];
    __syncthreads();

    const int w = tid >> 5, l = tid & 31;
    const int t = blockIdx.x * 8 + w;
    const float* hb = g_hbuf + (size_t)t * NC;
    #pragma unroll
    for (int i = 0; i < 32; i++) {
        int idx = i * 32 + l;
        if (idx < NC) hrow[w][idx] = hb[idx];
    }
    __syncwarp();

    #pragma unroll
    for (int r = 0; r < 2; r++) {
        const int p = l + r * 32;
        if (p < A_CNT * O_CNT) {
            const int a = p / 3, j = p - a * 3;
            const float* hr = &hrow[w][a * H_CNT];
            const float* w2 = &W2s[a * H_CNT * O_CNT + j];
            float o = b2s[p];
            #pragma unroll
            for (int h = 0; h < H_CNT; h++) o += hr[h] * w2[h * 3];
            osm[w][p] = o;
        }
    }
    __syncwarp();

    if (l < O_CNT) {
        float sq = 0.0f;
        #pragma unroll
        for (int a = 0; a < A_CNT; a++) { float v = osm[w][a * 3 + l]; sq += v * v; }
        scl[w][l] = sqrtf(sq) / (1.0f + sq);
    }
    __syncwarp();

    const int b = t >> 11, sidx = t & (S_LEN - 1);
    #pragma unroll
    for (int r = 0; r < 2; r++) {
        const int p = l + r * 32;
        if (p < A_CNT * O_CNT) {
            const int a = p / 3, j = p - a * 3;
            out[(size_t)(b * A_CNT + a) * (S_LEN * O_CNT) + sidx * 3 + j] =
                osm[w][p] * scl[w][j];
        }
    }
}

// =====================================================================
// launch
// =====================================================================
extern "C" void kernel_launch(void* const* d_in, const int* in_sizes, int n_in,
                              void* d_out, int out_size) {
    (void)in_sizes; (void)n_in; (void)out_size;
    const float* x    = (const float*)d_in[0];
    const float* ln_g = (const float*)d_in[1];
    const float* ln_b = (const float*)d_in[2];
    const float* W1   = (const float*)d_in[3];
    const float* b1   = (const float*)d_in[4];
    const float* W2   = (const float*)d_in[5];
    const float* b2   = (const float*)d_in[6];
    float* out = (float*)d_out;

    static int cfg_done = 0;
    if (!cfg_done) {
        cudaFuncSetAttribute(k_gemm, cudaFuncAttributeMaxDynamicSharedMemorySize, SMEMT);
        cfg_done = 1;
    }

    k_split<<<T_TOK, 256>>>(x);
    k_prepB<<<NPAD, 256>>>(ln_g, W1);
    k_off<<<A_CNT, 64>>>(ln_b, W1, b1);
    k_gemm<<<dim3(8, 256), 256, SMEMT>>>();
    k_out<<<T_TOK / 8, 256>>>(W2, b2, out);
}

// round 7
// speedup vs baseline: 2.8262x; 1.0748x over previous
#include <cuda_runtime.h>
#include <cuda_bf16.h>
#include <cstdint>

// ---------------- problem constants ----------------
#define T_TOK   32768            // B*S tokens
#define NXD     1024             // feature dim (K)
#define A_CNT   20
#define H_CNT   50
#define O_CNT   3
#define NC      1000             // A_CNT*H_CNT real columns
#define NPAD    1024             // padded N
#define S_LEN   2048
#define LN_EPS  1e-5f

// ---------------- device scratch ----------------
__device__ float g_off[NC];
__device__ float g_hbuf[(size_t)T_TOK * NC];                       // 131 MB
__device__ __align__(16) __nv_bfloat16 g_Ahi[(size_t)T_TOK * NXD]; // 64 MB
__device__ __align__(16) __nv_bfloat16 g_Alo[(size_t)T_TOK * NXD]; // 64 MB
__device__ __align__(16) __nv_bfloat16 g_Bhi[(size_t)NPAD * NXD];  // 2 MB
__device__ __align__(16) __nv_bfloat16 g_Blo[(size_t)NPAD * NXD];  // 2 MB

__device__ __forceinline__ uint32_t s2u(const void* p) {
    uint32_t a;
    asm("{ .reg .u64 t; cvta.to.shared.u64 t, %1; cvt.u32.u64 %0, t; }"
        : "=r"(a) : "l"(p));
    return a;
}
__device__ __forceinline__ unsigned pk2(__nv_bfloat16 a, __nv_bfloat16 b) {
    return (unsigned)__bfloat16_as_ushort(a) | ((unsigned)__bfloat16_as_ushort(b) << 16);
}

#define CP16(saddr, gaddr) \
    asm volatile("cp.async.cg.shared.global [%0], [%1], 16;" :: "r"(saddr), "l"(gaddr))
#define CP_COMMIT() asm volatile("cp.async.commit_group;" ::: "memory")
#define CP_WAIT0()  asm volatile("cp.async.wait_group 0;" ::: "memory")

#define LDSM4(r, addr) \
    asm volatile("ldmatrix.sync.aligned.m8n8.x4.shared.b16 {%0,%1,%2,%3}, [%4];" \
        : "=r"((r)[0]), "=r"((r)[1]), "=r"((r)[2]), "=r"((r)[3]) : "r"(addr))

#define MMA16816(d, a, b0, b1) \
    asm volatile("mma.sync.aligned.m16n8k16.row.col.f32.bf16.bf16.f32 " \
        "{%0,%1,%2,%3}, {%4,%5,%6,%7}, {%8,%9}, {%0,%1,%2,%3};" \
        : "+f"((d)[0]), "+f"((d)[1]), "+f"((d)[2]), "+f"((d)[3]) \
        : "r"((a)[0]), "r"((a)[1]), "r"((a)[2]), "r"((a)[3]), "r"(b0), "r"(b1))

// =====================================================================
// K1: per-token LN stats + bf16 hi/lo split of xn (fused)
// =====================================================================
__global__ void __launch_bounds__(256) k_split(const float* __restrict__ x) {
    const int t = blockIdx.x;
    const float4 v = reinterpret_cast<const float4*>(x)[(size_t)t * 256 + threadIdx.x];
    float s = v.x + v.y + v.z + v.w;
    float q = v.x * v.x + v.y * v.y + v.z * v.z + v.w * v.w;
    #pragma unroll
    for (int o = 16; o > 0; o >>= 1) {
        s += __shfl_xor_sync(0xffffffffu, s, o);
        q += __shfl_xor_sync(0xffffffffu, q, o);
    }
    __shared__ float ss[8], qq[8], smu, srs;
    const int w = threadIdx.x >> 5;
    if ((threadIdx.x & 31) == 0) { ss[w] = s; qq[w] = q; }
    __syncthreads();
    if (threadIdx.x == 0) {
        float S = 0.f, Q = 0.f;
        #pragma unroll
        for (int i = 0; i < 8; i++) { S += ss[i]; Q += qq[i]; }
        float mu  = S * (1.0f / (float)NXD);
        float var = fmaxf(Q * (1.0f / (float)NXD) - mu * mu, 0.0f);
        smu = mu;
        srs = 1.0f / sqrtf(var + LN_EPS);
    }
    __syncthreads();
    const float mu = smu, rs = srs;
    float n0 = (v.x - mu) * rs, n1 = (v.y - mu) * rs;
    float n2 = (v.z - mu) * rs, n3 = (v.w - mu) * rs;
    __nv_bfloat16 h0 = __float2bfloat16(n0), h1 = __float2bfloat16(n1);
    __nv_bfloat16 h2 = __float2bfloat16(n2), h3 = __float2bfloat16(n3);
    __nv_bfloat16 l0 = __float2bfloat16(n0 - __bfloat162float(h0));
    __nv_bfloat16 l1 = __float2bfloat16(n1 - __bfloat162float(h1));
    __nv_bfloat16 l2 = __float2bfloat16(n2 - __bfloat162float(h2));
    __nv_bfloat16 l3 = __float2bfloat16(n3 - __bfloat162float(h3));
    uint2 H, L;
    H.x = pk2(h0, h1); H.y = pk2(h2, h3);
    L.x = pk2(l0, l1); L.y = pk2(l2, l3);
    reinterpret_cast<uint2*>(g_Ahi)[(size_t)t * 256 + threadIdx.x] = H;
    reinterpret_cast<uint2*>(g_Alo)[(size_t)t * 256 + threadIdx.x] = L;
}

// =====================================================================
// K2a: B = (ln_g ⊙ W1)^T -> [NPAD][K] bf16 hi/lo (pad rows zero)
// =====================================================================
__global__ void __launch_bounds__(256) k_prepB(const float* __restrict__ ln_g,
                                               const float* __restrict__ W1) {
    const int n = blockIdx.x;
    int a = 0, h = 0;
    const bool val = (n < NC);
    if (val) { a = n / H_CNT; h = n - a * H_CNT; }
    #pragma unroll
    for (int j = 0; j < 4; j++) {
        const int k = threadIdx.x + j * 256;
        float wv = val ? ln_g[a * NXD + k] * W1[((size_t)a * NXD + k) * H_CNT + h] : 0.0f;
        __nv_bfloat16 hi = __float2bfloat16(wv);
        __nv_bfloat16 lo = __float2bfloat16(wv - __bfloat162float(hi));
        g_Bhi[(size_t)n * NXD + k] = hi;
        g_Blo[(size_t)n * NXD + k] = lo;
    }
}

// =====================================================================
// K2b: off[a,h] = ln_b[a,:]·W1[a,:,h] + b1[a,h]
// =====================================================================
__global__ void __launch_bounds__(64) k_off(const float* __restrict__ ln_b,
                                            const float* __restrict__ W1,
                                            const float* __restrict__ b1) {
    const int a = blockIdx.x;
    const int h = threadIdx.x;
    if (h >= H_CNT) return;
    const float* lb = ln_b + a * NXD;
    const float* w  = W1 + (size_t)a * NXD * H_CNT + h;
    float acc = 0.0f;
    #pragma unroll 8
    for (int n = 0; n < NXD; n++) acc += lb[n] * w[(size_t)n * H_CNT];
    g_off[a * H_CNT + h] = acc + b1[a * H_CNT + h];
}

// =====================================================================
// K3: mma.sync bf16 split GEMM  hbuf = relu(xn @ W1g + off)
//   CTA 128x128, BK=32, 8 warps (warp tile 32x64), cp.async 2-stage.
//   smem row: 64B data + 16B pad = 80B -> ldmatrix conflict-free.
//   Stage = Ahi|Alo|Bhi|Blo = 4 x 10240 B = 40960 B; 2 stages = 81920 B.
//   2 CTAs/SM (16 warps) for latency hiding; regs capped at 128.
// =====================================================================
#define SSTR   80
#define TILE_B (128 * SSTR)          // 10240
#define STAGE  (4 * TILE_B)          // 40960
#define SMEMT  (2 * STAGE)           // 81920

__global__ void __launch_bounds__(256, 2) k_gemm() {
    extern __shared__ __align__(16) char smem[];
    const uint32_t sb = s2u(smem);
    const int tid = threadIdx.x;
    const int w = tid >> 5, l = tid & 31;
    const int wm = w & 3, wn = w >> 2;          // 4 x 2 warp grid
    const int bx = blockIdx.x;                  // N tile 0..7 (fastest -> A reuse in L2)
    const int by = blockIdx.y;                  // M tile 0..255

    // ---- loader mapping: 2 chunks of 16B per tile per thread (BK=32) ----
    unsigned lrow[2], lkq[2], soff[2];
    #pragma unroll
    for (int i = 0; i < 2; i++) {
        unsigned c = tid + i * 256;             // 0..511
        lrow[i] = c >> 2;                       // 0..127
        lkq[i]  = c & 3;                        // 0..3 (16B units in 64B row)
        soff[i] = lrow[i] * SSTR + lkq[i] * 16;
    }
    const char* gAh = reinterpret_cast<const char*>(g_Ahi);
    const char* gAl = reinterpret_cast<const char*>(g_Alo);
    const char* gBh = reinterpret_cast<const char*>(g_Bhi);
    const char* gBl = reinterpret_cast<const char*>(g_Blo);

    auto load_stage = [&](int kt, int s) {
        const uint32_t st = sb + s * STAGE;
        #pragma unroll
        for (int i = 0; i < 2; i++) {
            size_t ga = ((size_t)(by * 128 + lrow[i]) * NXD + kt * 32 + lkq[i] * 8) * 2;
            CP16(st + soff[i],              gAh + ga);
            CP16(st + TILE_B + soff[i],     gAl + ga);
            size_t gb = ((size_t)(bx * 128 + lrow[i]) * NXD + kt * 32 + lkq[i] * 8) * 2;
            CP16(st + 2 * TILE_B + soff[i], gBh + gb);
            CP16(st + 3 * TILE_B + soff[i], gBl + gb);
        }
        CP_COMMIT();
    };

    // ---- ldmatrix base addresses (per lane) ----
    uint32_t abase[2], bbase[4];
    #pragma unroll
    for (int mi = 0; mi < 2; mi++)
        abase[mi] = (wm * 32 + mi * 16 + (l & 15)) * SSTR + (l >> 4) * 16;
    #pragma unroll
    for (int pi = 0; pi < 4; pi++)
        bbase[pi] = (wn * 64 + pi * 16 + (l & 15)) * SSTR + (l >> 4) * 16;

    float acc[2][8][4];
    #pragma unroll
    for (int mi = 0; mi < 2; mi++)
        #pragma unroll
        for (int ni = 0; ni < 8; ni++)
            #pragma unroll
            for (int r = 0; r < 4; r++) acc[mi][ni][r] = 0.0f;

    load_stage(0, 0);

    for (int kt = 0; kt < 32; kt++) {
        const int s = kt & 1;
        CP_WAIT0();
        __syncthreads();
        if (kt < 31) load_stage(kt + 1, s ^ 1);

        const uint32_t stA = sb + s * STAGE;
        const uint32_t stB = stA + 2 * TILE_B;
        #pragma unroll
        for (int ks = 0; ks < 2; ks++) {
            const uint32_t ko = ks * 32;
            uint32_t ah[2][4], al[2][4];
            #pragma unroll
            for (int mi = 0; mi < 2; mi++) {
                LDSM4(ah[mi], stA + abase[mi] + ko);
                LDSM4(al[mi], stA + TILE_B + abase[mi] + ko);
            }
            #pragma unroll
            for (int pi = 0; pi < 4; pi++) {
                uint32_t bh[4], bl[4];
                LDSM4(bh, stB + bbase[pi] + ko);
                LDSM4(bl, stB + TILE_B + bbase[pi] + ko);
                #pragma unroll
                for (int sel = 0; sel < 2; sel++) {
                    const int ni = pi * 2 + sel;
                    #pragma unroll
                    for (int mi = 0; mi < 2; mi++) {
                        MMA16816(acc[mi][ni], ah[mi], bh[sel], bh[sel + 2]);
                        MMA16816(acc[mi][ni], ah[mi], bl[sel], bl[sel + 2]);
                        MMA16816(acc[mi][ni], al[mi], bh[sel], bh[sel + 2]);
                    }
                }
            }
        }
        __syncthreads();
    }

    // ---- epilogue: +off, relu, STG.64 to g_hbuf ----
    const int r0  = by * 128 + wm * 32 + (l >> 2);
    const int cb0 = bx * 128 + wn * 64 + (l & 3) * 2;
    #pragma unroll
    for (int mi = 0; mi < 2; mi++) {
        #pragma unroll
        for (int ni = 0; ni < 8; ni++) {
            const int gc = cb0 + ni * 8;
            if (gc < NC) {   // gc even, NC even -> gc+1 also valid
                const float o0 = g_off[gc], o1 = g_off[gc + 1];
                float* hb0 = g_hbuf + (size_t)(r0 + mi * 16) * NC + gc;
                float* hb1 = hb0 + (size_t)8 * NC;
                float2 v0, v1;
                v0.x = fmaxf(acc[mi][ni][0] + o0, 0.0f);
                v0.y = fmaxf(acc[mi][ni][1] + o1, 0.0f);
                v1.x = fmaxf(acc[mi][ni][2] + o0, 0.0f);
                v1.y = fmaxf(acc[mi][ni][3] + o1, 0.0f);
                *reinterpret_cast<float2*>(hb0) = v0;
                *reinterpret_cast<float2*>(hb1) = v1;
            }
        }
    }
}

// =====================================================================
// K4: per-token 50->3 GEMM per adapter + cross-adapter squash
// =====================================================================
__global__ void __launch_bounds__(256) k_out(const float* __restrict__ W2,
                                             const float* __restrict__ b2,
                                             float* __restrict__ out) {
    __shared__ float W2s[A_CNT * H_CNT * O_CNT];
    __shared__ float b2s[A_CNT * O_CNT];
    __shared__ float hrow[8][NC];
    __shared__ float osm[8][64];
    __shared__ float scl[8][4];

    const int tid = threadIdx.x;
    for (int i = tid; i < A_CNT * H_CNT * O_CNT; i += 256) W2s[i] = W2[i];
    if (tid < A_CNT * O_CNT) b2s[tid] = b2[tid];
    __syncthreads();

    const int w = tid >> 5, l = tid & 31;
    const int t = blockIdx.x * 8 + w;
    const float* hb = g_hbuf + (size_t)t * NC;
    #pragma unroll
    for (int i = 0; i < 32; i++) {
        int idx = i * 32 + l;
        if (idx < NC) hrow[w][idx] = hb[idx];
    }
    __syncwarp();

    #pragma unroll
    for (int r = 0; r < 2; r++) {
        const int p = l + r * 32;
        if (p < A_CNT * O_CNT) {
            const int a = p / 3, j = p - a * 3;
            const float* hr = &hrow[w][a * H_CNT];
            const float* w2 = &W2s[a * H_CNT * O_CNT + j];
            float o = b2s[p];
            #pragma unroll
            for (int h = 0; h < H_CNT; h++) o += hr[h] * w2[h * 3];
            osm[w][p] = o;
        }
    }
    __syncwarp();

    if (l < O_CNT) {
        float sq = 0.0f;
        #pragma unroll
        for (int a = 0; a < A_CNT; a++) { float v = osm[w][a * 3 + l]; sq += v * v; }
        scl[w][l] = sqrtf(sq) / (1.0f + sq);
    }
    __syncwarp();

    const int b = t >> 11, sidx = t & (S_LEN - 1);
    #pragma unroll
    for (int r = 0; r < 2; r++) {
        const int p = l + r * 32;
        if (p < A_CNT * O_CNT) {
            const int a = p / 3, j = p - a * 3;
            out[(size_t)(b * A_CNT + a) * (S_LEN * O_CNT) + sidx * 3 + j] =
                osm[w][p] * scl[w][j];
        }
    }
}

// =====================================================================
// launch
// =====================================================================
extern "C" void kernel_launch(void* const* d_in, const int* in_sizes, int n_in,
                              void* d_out, int out_size) {
    (void)in_sizes; (void)n_in; (void)out_size;
    const float* x    = (const float*)d_in[0];
    const float* ln_g = (const float*)d_in[1];
    const float* ln_b = (const float*)d_in[2];
    const float* W1   = (const float*)d_in[3];
    const float* b1   = (const float*)d_in[4];
    const float* W2   = (const float*)d_in[5];
    const float* b2   = (const float*)d_in[6];
    float* out = (float*)d_out;

    cudaFuncSetAttribute(k_gemm, cudaFuncAttributeMaxDynamicSharedMemorySize, SMEMT);

    k_split<<<T_TOK, 256>>>(x);
    k_prepB<<<NPAD, 256>>>(ln_g, W1);
    k_off<<<A_CNT, 64>>>(ln_b, W1, b1);
    k_gemm<<<dim3(8, 256), 256, SMEMT>>>();
    k_out<<<T_TOK / 8, 256>>>(W2, b2, out);
}

// round 8
// speedup vs baseline: 5.5609x; 1.9676x over previous
#include <cuda_runtime.h>
#include <cuda_fp16.h>
#include <cstdint>

// ---------------- problem constants ----------------
#define T_TOK   32768            // B*S tokens
#define NXD     1024             // feature dim (K)
#define A_CNT   20
#define H_CNT   50
#define O_CNT   3
#define NC      1000             // A_CNT*H_CNT real columns
#define NPAD    1024             // padded N
#define S_LEN   2048
#define LN_EPS  1e-5f

// ---------------- device scratch ----------------
__device__ float g_off[NC];
__device__ float g_hbuf[(size_t)T_TOK * NC];                 // 131 MB
__device__ __align__(16) __half g_A[(size_t)T_TOK * NXD];    // 64 MB  xn fp16
__device__ __align__(16) __half g_B[(size_t)NPAD * NXD];     // 2 MB   (ln_g*W1)^T fp16

__device__ __forceinline__ uint32_t s2u(const void* p) {
    uint32_t a;
    asm("{ .reg .u64 t; cvta.to.shared.u64 t, %1; cvt.u32.u64 %0, t; }"
        : "=r"(a) : "l"(p));
    return a;
}
__device__ __forceinline__ unsigned pk2h(__half a, __half b) {
    return (unsigned)__half_as_ushort(a) | ((unsigned)__half_as_ushort(b) << 16);
}

#define CP16(saddr, gaddr) \
    asm volatile("cp.async.cg.shared.global [%0], [%1], 16;" :: "r"(saddr), "l"(gaddr))
#define CP_COMMIT() asm volatile("cp.async.commit_group;" ::: "memory")
#define CP_WAIT0()  asm volatile("cp.async.wait_group 0;" ::: "memory")

#define LDSM4(r, addr) \
    asm volatile("ldmatrix.sync.aligned.m8n8.x4.shared.b16 {%0,%1,%2,%3}, [%4];" \
        : "=r"((r)[0]), "=r"((r)[1]), "=r"((r)[2]), "=r"((r)[3]) : "r"(addr))

#define MMAH(d, a, b0, b1) \
    asm volatile("mma.sync.aligned.m16n8k16.row.col.f32.f16.f16.f32 " \
        "{%0,%1,%2,%3}, {%4,%5,%6,%7}, {%8,%9}, {%0,%1,%2,%3};" \
        : "+f"((d)[0]), "+f"((d)[1]), "+f"((d)[2]), "+f"((d)[3]) \
        : "r"((a)[0]), "r"((a)[1]), "r"((a)[2]), "r"((a)[3]), "r"(b0), "r"(b1))

// =====================================================================
// K1: per-token LN stats + fp16 conversion of xn (fused)
// =====================================================================
__global__ void __launch_bounds__(256) k_split(const float* __restrict__ x) {
    const int t = blockIdx.x;
    const float4 v = reinterpret_cast<const float4*>(x)[(size_t)t * 256 + threadIdx.x];
    float s = v.x + v.y + v.z + v.w;
    float q = v.x * v.x + v.y * v.y + v.z * v.z + v.w * v.w;
    #pragma unroll
    for (int o = 16; o > 0; o >>= 1) {
        s += __shfl_xor_sync(0xffffffffu, s, o);
        q += __shfl_xor_sync(0xffffffffu, q, o);
    }
    __shared__ float ss[8], qq[8], smu, srs;
    const int w = threadIdx.x >> 5;
    if ((threadIdx.x & 31) == 0) { ss[w] = s; qq[w] = q; }
    __syncthreads();
    if (threadIdx.x == 0) {
        float S = 0.f, Q = 0.f;
        #pragma unroll
        for (int i = 0; i < 8; i++) { S += ss[i]; Q += qq[i]; }
        float mu  = S * (1.0f / (float)NXD);
        float var = fmaxf(Q * (1.0f / (float)NXD) - mu * mu, 0.0f);
        smu = mu;
        srs = 1.0f / sqrtf(var + LN_EPS);
    }
    __syncthreads();
    const float mu = smu, rs = srs;
    uint2 H;
    H.x = pk2h(__float2half((v.x - mu) * rs), __float2half((v.y - mu) * rs));
    H.y = pk2h(__float2half((v.z - mu) * rs), __float2half((v.w - mu) * rs));
    reinterpret_cast<uint2*>(g_A)[(size_t)t * 256 + threadIdx.x] = H;
}

// =====================================================================
// K2a: B = (ln_g ⊙ W1)^T -> [NPAD][K] fp16 (pad rows zero)
// =====================================================================
__global__ void __launch_bounds__(256) k_prepB(const float* __restrict__ ln_g,
                                               const float* __restrict__ W1) {
    const int n = blockIdx.x;
    int a = 0, h = 0;
    const bool val = (n < NC);
    if (val) { a = n / H_CNT; h = n - a * H_CNT; }
    #pragma unroll
    for (int j = 0; j < 4; j++) {
        const int k = threadIdx.x + j * 256;
        float wv = val ? ln_g[a * NXD + k] * W1[((size_t)a * NXD + k) * H_CNT + h] : 0.0f;
        g_B[(size_t)n * NXD + k] = __float2half(wv);
    }
}

// =====================================================================
// K2b: off[a,h] = ln_b[a,:]·W1[a,:,h] + b1[a,h]
// =====================================================================
__global__ void __launch_bounds__(64) k_off(const float* __restrict__ ln_b,
                                            const float* __restrict__ W1,
                                            const float* __restrict__ b1) {
    const int a = blockIdx.x;
    const int h = threadIdx.x;
    if (h >= H_CNT) return;
    const float* lb = ln_b + a * NXD;
    const float* w  = W1 + (size_t)a * NXD * H_CNT + h;
    float acc = 0.0f;
    #pragma unroll 8
    for (int n = 0; n < NXD; n++) acc += lb[n] * w[(size_t)n * H_CNT];
    g_off[a * H_CNT + h] = acc + b1[a * H_CNT + h];
}

// =====================================================================
// K3: fp16 mma.sync GEMM  hbuf = relu(xn @ W1g + off)
//   CTA 128x128, BK=64, 4 warps (2x2), warp tile 64x64, cp.async 2-stage.
//   smem row: 128B data + 16B pad = 144B. Stage = A|B = 2 x 18432 = 36864.
//   2 stages = 73728; 2 CTAs/SM.
// =====================================================================
#define SSTR   144
#define TILE_B (128 * SSTR)          // 18432
#define STAGE  (2 * TILE_B)          // 36864
#define SMEMT  (2 * STAGE)           // 73728

__global__ void __launch_bounds__(128, 2) k_gemm() {
    extern __shared__ __align__(16) char smem[];
    const uint32_t sb = s2u(smem);
    const int tid = threadIdx.x;
    const int w = tid >> 5, l = tid & 31;
    const int wm = w & 1, wn = w >> 1;          // 2 x 2 warp grid, 64x64 tiles
    const int bx = blockIdx.x;                  // N tile 0..7 (fastest -> A L2 reuse)
    const int by = blockIdx.y;                  // M tile 0..255

    // ---- loader mapping: 8 chunks of 16B per tile per thread (BK=64) ----
    unsigned soff[8], rel[8];
    #pragma unroll
    for (int i = 0; i < 8; i++) {
        unsigned c = tid + i * 128;             // 0..1023
        unsigned row = c >> 3, kq = c & 7;      // 128 rows x 8 u16B
        soff[i] = row * SSTR + kq * 16;
        rel[i]  = row * NXD + kq * 8;           // halfs within [128][1024] tile
    }
    const char* gA = reinterpret_cast<const char*>(g_A) + (size_t)by * 128 * NXD * 2;
    const char* gB = reinterpret_cast<const char*>(g_B) + (size_t)bx * 128 * NXD * 2;

    auto load_stage = [&](int kt, int s) {
        const uint32_t st = sb + s * STAGE;
        const unsigned kofs = kt * 64;          // halfs
        #pragma unroll
        for (int i = 0; i < 8; i++) {
            CP16(st + soff[i],          gA + (size_t)(rel[i] + kofs) * 2);
            CP16(st + TILE_B + soff[i], gB + (size_t)(rel[i] + kofs) * 2);
        }
        CP_COMMIT();
    };

    // ---- ldmatrix base addresses (per lane) ----
    uint32_t abase[4], bbase[4];
    #pragma unroll
    for (int mi = 0; mi < 4; mi++)
        abase[mi] = (wm * 64 + mi * 16 + (l & 15)) * SSTR + (l >> 4) * 16;
    #pragma unroll
    for (int pi = 0; pi < 4; pi++)
        bbase[pi] = (wn * 64 + pi * 16 + (l & 15)) * SSTR + (l >> 4) * 16;

    float acc[4][8][4];
    #pragma unroll
    for (int mi = 0; mi < 4; mi++)
        #pragma unroll
        for (int ni = 0; ni < 8; ni++)
            #pragma unroll
            for (int r = 0; r < 4; r++) acc[mi][ni][r] = 0.0f;

    load_stage(0, 0);

    for (int kt = 0; kt < 16; kt++) {
        const int s = kt & 1;
        CP_WAIT0();
        __syncthreads();
        if (kt < 15) load_stage(kt + 1, s ^ 1);

        const uint32_t stA = sb + s * STAGE;
        const uint32_t stB = stA + TILE_B;
        #pragma unroll
        for (int ks = 0; ks < 4; ks++) {
            const uint32_t ko = ks * 32;        // 16 halfs = 32B per MMA k-step
            uint32_t a_[4][4], b_[4][4];
            #pragma unroll
            for (int mi = 0; mi < 4; mi++) LDSM4(a_[mi], stA + abase[mi] + ko);
            #pragma unroll
            for (int pi = 0; pi < 4; pi++) LDSM4(b_[pi], stB + bbase[pi] + ko);
            #pragma unroll
            for (int mi = 0; mi < 4; mi++)
                #pragma unroll
                for (int ni = 0; ni < 8; ni++) {
                    const int pi = ni >> 1, sel = ni & 1;
                    MMAH(acc[mi][ni], a_[mi], b_[pi][sel], b_[pi][sel + 2]);
                }
        }
        __syncthreads();
    }

    // ---- epilogue: +off, relu, STG.64 to g_hbuf ----
    const int r0  = by * 128 + wm * 64 + (l >> 2);
    const int cb0 = bx * 128 + wn * 64 + (l & 3) * 2;
    #pragma unroll
    for (int mi = 0; mi < 4; mi++) {
        #pragma unroll
        for (int ni = 0; ni < 8; ni++) {
            const int gc = cb0 + ni * 8;
            if (gc < NC) {   // gc even, NC even -> gc+1 also valid
                const float o0 = g_off[gc], o1 = g_off[gc + 1];
                float* hb0 = g_hbuf + (size_t)(r0 + mi * 16) * NC + gc;
                float* hb1 = hb0 + (size_t)8 * NC;
                float2 v0, v1;
                v0.x = fmaxf(acc[mi][ni][0] + o0, 0.0f);
                v0.y = fmaxf(acc[mi][ni][1] + o1, 0.0f);
                v1.x = fmaxf(acc[mi][ni][2] + o0, 0.0f);
                v1.y = fmaxf(acc[mi][ni][3] + o1, 0.0f);
                *reinterpret_cast<float2*>(hb0) = v0;
                *reinterpret_cast<float2*>(hb1) = v1;
            }
        }
    }
}

// =====================================================================
// K4: per-token 50->3 GEMM per adapter + cross-adapter squash
// =====================================================================
__global__ void __launch_bounds__(256) k_out(const float* __restrict__ W2,
                                             const float* __restrict__ b2,
                                             float* __restrict__ out) {
    __shared__ float W2s[A_CNT * H_CNT * O_CNT];
    __shared__ float b2s[A_CNT * O_CNT];
    __shared__ float hrow[8][NC];
    __shared__ float osm[8][64];
    __shared__ float scl[8][4];

    const int tid = threadIdx.x;
    for (int i = tid; i < A_CNT * H_CNT * O_CNT; i += 256) W2s[i] = W2[i];
    if (tid < A_CNT * O_CNT) b2s[tid] = b2[tid];
    __syncthreads();

    const int w = tid >> 5, l = tid & 31;
    const int t = blockIdx.x * 8 + w;
    const float* hb = g_hbuf + (size_t)t * NC;
    #pragma unroll
    for (int i = 0; i < 32; i++) {
        int idx = i * 32 + l;
        if (idx < NC) hrow[w][idx] = hb[idx];
    }
    __syncwarp();

    #pragma unroll
    for (int r = 0; r < 2; r++) {
        const int p = l + r * 32;
        if (p < A_CNT * O_CNT) {
            const int a = p / 3, j = p - a * 3;
            const float* hr = &hrow[w][a * H_CNT];
            const float* w2 = &W2s[a * H_CNT * O_CNT + j];
            float o = b2s[p];
            #pragma unroll
            for (int h = 0; h < H_CNT; h++) o += hr[h] * w2[h * 3];
            osm[w][p] = o;
        }
    }
    __syncwarp();

    if (l < O_CNT) {
        float sq = 0.0f;
        #pragma unroll
        for (int a = 0; a < A_CNT; a++) { float v = osm[w][a * 3 + l]; sq += v * v; }
        scl[w][l] = sqrtf(sq) / (1.0f + sq);
    }
    __syncwarp();

    const int b = t >> 11, sidx = t & (S_LEN - 1);
    #pragma unroll
    for (int r = 0; r < 2; r++) {
        const int p = l + r * 32;
        if (p < A_CNT * O_CNT) {
            const int a = p / 3, j = p - a * 3;
            out[(size_t)(b * A_CNT + a) * (S_LEN * O_CNT) + sidx * 3 + j] =
                osm[w][p] * scl[w][j];
        }
    }
}

// =====================================================================
// launch
// =====================================================================
extern "C" void kernel_launch(void* const* d_in, const int* in_sizes, int n_in,
                              void* d_out, int out_size) {
    (void)in_sizes; (void)n_in; (void)out_size;
    const float* x    = (const float*)d_in[0];
    const float* ln_g = (const float*)d_in[1];
    const float* ln_b = (const float*)d_in[2];
    const float* W1   = (const float*)d_in[3];
    const float* b1   = (const float*)d_in[4];
    const float* W2   = (const float*)d_in[5];
    const float* b2   = (const float*)d_in[6];
    float* out = (float*)d_out;

    cudaFuncSetAttribute(k_gemm, cudaFuncAttributeMaxDynamicSharedMemorySize, SMEMT);

    k_split<<<T_TOK, 256>>>(x);
    k_prepB<<<NPAD, 256>>>(ln_g, W1);
    k_off<<<A_CNT, 64>>>(ln_b, W1, b1);
    k_gemm<<<dim3(8, 256), 128, SMEMT>>>();
    k_out<<<T_TOK / 8, 256>>>(W2, b2, out);
}

// round 9
// speedup vs baseline: 5.5622x; 1.0002x over previous
#include <cuda_runtime.h>
#include <cuda_fp16.h>
#include <cstdint>

// ---------------- problem constants ----------------
#define T_TOK   32768            // B*S tokens
#define NXD     1024             // feature dim (K)
#define A_CNT   20
#define H_CNT   50
#define O_CNT   3
#define NC      1000             // A_CNT*H_CNT real columns
#define NPAD    1024             // padded N
#define S_LEN   2048
#define LN_EPS  1e-5f

// ---------------- device scratch ----------------
__device__ float g_off[NC];
__device__ __align__(16) __half g_hbuf[(size_t)T_TOK * NC];  // 65 MB relu(h) fp16
__device__ __align__(16) __half g_A[(size_t)T_TOK * NXD];    // 64 MB  xn fp16
__device__ __align__(16) __half g_B[(size_t)NPAD * NXD];     // 2 MB   (ln_g*W1)^T fp16

__device__ __forceinline__ uint32_t s2u(const void* p) {
    uint32_t a;
    asm("{ .reg .u64 t; cvta.to.shared.u64 t, %1; cvt.u32.u64 %0, t; }"
        : "=r"(a) : "l"(p));
    return a;
}
__device__ __forceinline__ unsigned pk2h(__half a, __half b) {
    return (unsigned)__half_as_ushort(a) | ((unsigned)__half_as_ushort(b) << 16);
}

#define CP16(saddr, gaddr) \
    asm volatile("cp.async.cg.shared.global [%0], [%1], 16;" :: "r"(saddr), "l"(gaddr))
#define CP_COMMIT() asm volatile("cp.async.commit_group;" ::: "memory")
#define CP_WAIT1()  asm volatile("cp.async.wait_group 1;" ::: "memory")
#define CP_WAIT0()  asm volatile("cp.async.wait_group 0;" ::: "memory")

#define LDSM4(r, addr) \
    asm volatile("ldmatrix.sync.aligned.m8n8.x4.shared.b16 {%0,%1,%2,%3}, [%4];" \
        : "=r"((r)[0]), "=r"((r)[1]), "=r"((r)[2]), "=r"((r)[3]) : "r"(addr))

#define MMAH(d, a, b0, b1) \
    asm volatile("mma.sync.aligned.m16n8k16.row.col.f32.f16.f16.f32 " \
        "{%0,%1,%2,%3}, {%4,%5,%6,%7}, {%8,%9}, {%0,%1,%2,%3};" \
        : "+f"((d)[0]), "+f"((d)[1]), "+f"((d)[2]), "+f"((d)[3]) \
        : "r"((a)[0]), "r"((a)[1]), "r"((a)[2]), "r"((a)[3]), "r"(b0), "r"(b1))

// =====================================================================
// K1: per-token LN stats + fp16 conversion of xn (fused)
// =====================================================================
__global__ void __launch_bounds__(256) k_split(const float* __restrict__ x) {
    const int t = blockIdx.x;
    const float4 v = reinterpret_cast<const float4*>(x)[(size_t)t * 256 + threadIdx.x];
    float s = v.x + v.y + v.z + v.w;
    float q = v.x * v.x + v.y * v.y + v.z * v.z + v.w * v.w;
    #pragma unroll
    for (int o = 16; o > 0; o >>= 1) {
        s += __shfl_xor_sync(0xffffffffu, s, o);
        q += __shfl_xor_sync(0xffffffffu, q, o);
    }
    __shared__ float ss[8], qq[8], smu, srs;
    const int w = threadIdx.x >> 5;
    if ((threadIdx.x & 31) == 0) { ss[w] = s; qq[w] = q; }
    __syncthreads();
    if (threadIdx.x == 0) {
        float S = 0.f, Q = 0.f;
        #pragma unroll
        for (int i = 0; i < 8; i++) { S += ss[i]; Q += qq[i]; }
        float mu  = S * (1.0f / (float)NXD);
        float var = fmaxf(Q * (1.0f / (float)NXD) - mu * mu, 0.0f);
        smu = mu;
        srs = 1.0f / sqrtf(var + LN_EPS);
    }
    __syncthreads();
    const float mu = smu, rs = srs;
    uint2 H;
    H.x = pk2h(__float2half((v.x - mu) * rs), __float2half((v.y - mu) * rs));
    H.y = pk2h(__float2half((v.z - mu) * rs), __float2half((v.w - mu) * rs));
    reinterpret_cast<uint2*>(g_A)[(size_t)t * 256 + threadIdx.x] = H;
}

// =====================================================================
// K2a: B = (ln_g ⊙ W1)^T -> [NPAD][K] fp16 (pad rows zero)
// =====================================================================
__global__ void __launch_bounds__(256) k_prepB(const float* __restrict__ ln_g,
                                               const float* __restrict__ W1) {
    const int n = blockIdx.x;
    int a = 0, h = 0;
    const bool val = (n < NC);
    if (val) { a = n / H_CNT; h = n - a * H_CNT; }
    #pragma unroll
    for (int j = 0; j < 4; j++) {
        const int k = threadIdx.x + j * 256;
        float wv = val ? ln_g[a * NXD + k] * W1[((size_t)a * NXD + k) * H_CNT + h] : 0.0f;
        g_B[(size_t)n * NXD + k] = __float2half(wv);
    }
}

// =====================================================================
// K2b: off[a,h] = ln_b[a,:]·W1[a,:,h] + b1[a,h]
// =====================================================================
__global__ void __launch_bounds__(64) k_off(const float* __restrict__ ln_b,
                                            const float* __restrict__ W1,
                                            const float* __restrict__ b1) {
    const int a = blockIdx.x;
    const int h = threadIdx.x;
    if (h >= H_CNT) return;
    const float* lb = ln_b + a * NXD;
    const float* w  = W1 + (size_t)a * NXD * H_CNT + h;
    float acc = 0.0f;
    #pragma unroll 8
    for (int n = 0; n < NXD; n++) acc += lb[n] * w[(size_t)n * H_CNT];
    g_off[a * H_CNT + h] = acc + b1[a * H_CNT + h];
}

// =====================================================================
// K3: fp16 mma.sync GEMM  hbuf = relu(xn @ W1g + off)  (fp16 output)
//   CTA 128x128, BK=64, 4 warps (2x2), warp tile 64x64.
//   cp.async 3-STAGE pipeline, wait_group 1 (load latency fully hidden).
//   smem row: 128B data + 16B pad = 144B. Stage = A|B = 36864 B.
//   3 stages = 110592 B; 2 CTAs/SM.
// =====================================================================
#define SSTR   144
#define TILE_B (128 * SSTR)          // 18432
#define STAGE  (2 * TILE_B)          // 36864
#define SMEMT  (3 * STAGE)           // 110592
#define NKT    16

__global__ void __launch_bounds__(128, 2) k_gemm() {
    extern __shared__ __align__(16) char smem[];
    const uint32_t sb = s2u(smem);
    const int tid = threadIdx.x;
    const int w = tid >> 5, l = tid & 31;
    const int wm = w & 1, wn = w >> 1;          // 2 x 2 warp grid, 64x64 tiles
    const int bx = blockIdx.x;                  // N tile 0..7 (fastest -> A L2 reuse)
    const int by = blockIdx.y;                  // M tile 0..255

    // ---- loader mapping: 8 chunks of 16B per tile per thread (BK=64) ----
    unsigned soff[8], rel[8];
    #pragma unroll
    for (int i = 0; i < 8; i++) {
        unsigned c = tid + i * 128;             // 0..1023
        unsigned row = c >> 3, kq = c & 7;      // 128 rows x 8 u16B
        soff[i] = row * SSTR + kq * 16;
        rel[i]  = row * NXD + kq * 8;           // halfs within [128][1024] tile
    }
    const char* gA = reinterpret_cast<const char*>(g_A) + (size_t)by * 128 * NXD * 2;
    const char* gB = reinterpret_cast<const char*>(g_B) + (size_t)bx * 128 * NXD * 2;

    auto load_stage = [&](int kt, int s) {
        const uint32_t st = sb + s * STAGE;
        const unsigned kofs = kt * 64;          // halfs
        #pragma unroll
        for (int i = 0; i < 8; i++) {
            CP16(st + soff[i],          gA + (size_t)(rel[i] + kofs) * 2);
            CP16(st + TILE_B + soff[i], gB + (size_t)(rel[i] + kofs) * 2);
        }
        CP_COMMIT();
    };

    // ---- ldmatrix base addresses (per lane) ----
    uint32_t abase[4], bbase[4];
    #pragma unroll
    for (int mi = 0; mi < 4; mi++)
        abase[mi] = (wm * 64 + mi * 16 + (l & 15)) * SSTR + (l >> 4) * 16;
    #pragma unroll
    for (int pi = 0; pi < 4; pi++)
        bbase[pi] = (wn * 64 + pi * 16 + (l & 15)) * SSTR + (l >> 4) * 16;

    float acc[4][8][4];
    #pragma unroll
    for (int mi = 0; mi < 4; mi++)
        #pragma unroll
        for (int ni = 0; ni < 8; ni++)
            #pragma unroll
            for (int r = 0; r < 4; r++) acc[mi][ni][r] = 0.0f;

    load_stage(0, 0);
    load_stage(1, 1);

    for (int kt = 0; kt < NKT; kt++) {
        const int s = kt % 3;
        if (kt == NKT - 1) { CP_WAIT0(); } else { CP_WAIT1(); }
        __syncthreads();    // all warps: stage(kt) visible AND done reading stage (kt+2)%3's old data
        if (kt + 2 < NKT) load_stage(kt + 2, (kt + 2) % 3);

        const uint32_t stA = sb + s * STAGE;
        const uint32_t stB = stA + TILE_B;
        #pragma unroll
        for (int ks = 0; ks < 4; ks++) {
            const uint32_t ko = ks * 32;        // 16 halfs = 32B per MMA k-step
            uint32_t a_[4][4], b_[4][4];
            #pragma unroll
            for (int mi = 0; mi < 4; mi++) LDSM4(a_[mi], stA + abase[mi] + ko);
            #pragma unroll
            for (int pi = 0; pi < 4; pi++) LDSM4(b_[pi], stB + bbase[pi] + ko);
            #pragma unroll
            for (int mi = 0; mi < 4; mi++)
                #pragma unroll
                for (int ni = 0; ni < 8; ni++) {
                    const int pi = ni >> 1, sel = ni & 1;
                    MMAH(acc[mi][ni], a_[mi], b_[pi][sel], b_[pi][sel + 2]);
                }
        }
    }

    // ---- epilogue: +off, relu, fp16 stores to g_hbuf ----
    const int r0  = by * 128 + wm * 64 + (l >> 2);
    const int cb0 = bx * 128 + wn * 64 + (l & 3) * 2;
    #pragma unroll
    for (int mi = 0; mi < 4; mi++) {
        #pragma unroll
        for (int ni = 0; ni < 8; ni++) {
            const int gc = cb0 + ni * 8;
            if (gc < NC) {   // gc even, NC even -> gc+1 also valid
                const float o0 = g_off[gc], o1 = g_off[gc + 1];
                __half* hb0 = g_hbuf + (size_t)(r0 + mi * 16) * NC + gc;
                __half* hb1 = hb0 + (size_t)8 * NC;
                __half2 v0 = __floats2half2_rn(fmaxf(acc[mi][ni][0] + o0, 0.0f),
                                               fmaxf(acc[mi][ni][1] + o1, 0.0f));
                __half2 v1 = __floats2half2_rn(fmaxf(acc[mi][ni][2] + o0, 0.0f),
                                               fmaxf(acc[mi][ni][3] + o1, 0.0f));
                *reinterpret_cast<__half2*>(hb0) = v0;
                *reinterpret_cast<__half2*>(hb1) = v1;
            }
        }
    }
}

// =====================================================================
// K4: per-token 50->3 GEMM per adapter + cross-adapter squash
// =====================================================================
__global__ void __launch_bounds__(256) k_out(const float* __restrict__ W2,
                                             const float* __restrict__ b2,
                                             float* __restrict__ out) {
    __shared__ float W2s[A_CNT * H_CNT * O_CNT];
    __shared__ float b2s[A_CNT * O_CNT];
    __shared__ float hrow[8][NC];
    __shared__ float osm[8][64];
    __shared__ float scl[8][4];

    const int tid = threadIdx.x;
    for (int i = tid; i < A_CNT * H_CNT * O_CNT; i += 256) W2s[i] = W2[i];
    if (tid < A_CNT * O_CNT) b2s[tid] = b2[tid];
    __syncthreads();

    const int w = tid >> 5, l = tid & 31;
    const int t = blockIdx.x * 8 + w;
    const __half2* hb2 = reinterpret_cast<const __half2*>(g_hbuf + (size_t)t * NC);
    #pragma unroll
    for (int i = 0; i < 16; i++) {
        int idx = i * 32 + l;                    // half2 index 0..499
        if (idx < NC / 2) {
            float2 f = __half22float2(hb2[idx]);
            hrow[w][idx * 2]     = f.x;
            hrow[w][idx * 2 + 1] = f.y;
        }
    }
    __syncwarp();

    #pragma unroll
    for (int r = 0; r < 2; r++) {
        const int p = l + r * 32;
        if (p < A_CNT * O_CNT) {
            const int a = p / 3, j = p - a * 3;
            const float* hr = &hrow[w][a * H_CNT];
            const float* w2 = &W2s[a * H_CNT * O_CNT + j];
            float o = b2s[p];
            #pragma unroll
            for (int h = 0; h < H_CNT; h++) o += hr[h] * w2[h * 3];
            osm[w][p] = o;
        }
    }
    __syncwarp();

    if (l < O_CNT) {
        float sq = 0.0f;
        #pragma unroll
        for (int a = 0; a < A_CNT; a++) { float v = osm[w][a * 3 + l]; sq += v * v; }
        scl[w][l] = sqrtf(sq) / (1.0f + sq);
    }
    __syncwarp();

    const int b = t >> 11, sidx = t & (S_LEN - 1);
    #pragma unroll
    for (int r = 0; r < 2; r++) {
        const int p = l + r * 32;
        if (p < A_CNT * O_CNT) {
            const int a = p / 3, j = p - a * 3;
            out[(size_t)(b * A_CNT + a) * (S_LEN * O_CNT) + sidx * 3 + j] =
                osm[w][p] * scl[w][j];
        }
    }
}

// =====================================================================
// launch
// =====================================================================
extern "C" void kernel_launch(void* const* d_in, const int* in_sizes, int n_in,
                              void* d_out, int out_size) {
    (void)in_sizes; (void)n_in; (void)out_size;
    const float* x    = (const float*)d_in[0];
    const float* ln_g = (const float*)d_in[1];
    const float* ln_b = (const float*)d_in[2];
    const float* W1   = (const float*)d_in[3];
    const float* b1   = (const float*)d_in[4];
    const float* W2   = (const float*)d_in[5];
    const float* b2   = (const float*)d_in[6];
    float* out = (float*)d_out;

    cudaFuncSetAttribute(k_gemm, cudaFuncAttributeMaxDynamicSharedMemorySize, SMEMT);

    k_split<<<T_TOK, 256>>>(x);
    k_prepB<<<NPAD, 256>>>(ln_g, W1);
    k_off<<<A_CNT, 64>>>(ln_b, W1, b1);
    k_gemm<<<dim3(8, 256), 128, SMEMT>>>();
    k_out<<<T_TOK / 8, 256>>>(W2, b2, out);
}

// round 11
// speedup vs baseline: 6.1292x; 1.1019x over previous
#include <cuda_runtime.h>
#include <cuda_fp16.h>
#include <cstdint>

// ---------------- problem constants ----------------
#define T_TOK   32768            // B*S tokens
#define NXD     1024             // feature dim (K)
#define A_CNT   20
#define H_CNT   50
#define O_CNT   3
#define NC      1000             // A_CNT*H_CNT real columns
#define NPAD    1024             // padded N
#define S_LEN   2048
#define LN_EPS  1e-5f

// ---------------- device scratch ----------------
__device__ float g_off[NC];
__device__ float g_obuf[2][(size_t)T_TOK * 60];              // partial o, 2 slots, 15.7 MB
__device__ __align__(16) __half g_A[(size_t)T_TOK * NXD];    // 64 MB  xn fp16
__device__ __align__(16) __half g_B[(size_t)NPAD * NXD];     // 2 MB   (ln_g*W1)^T fp16

__device__ __forceinline__ uint32_t s2u(const void* p) {
    uint32_t a;
    asm("{ .reg .u64 t; cvta.to.shared.u64 t, %1; cvt.u32.u64 %0, t; }"
        : "=r"(a) : "l"(p));
    return a;
}
__device__ __forceinline__ unsigned pk2h(__half a, __half b) {
    return (unsigned)__half_as_ushort(a) | ((unsigned)__half_as_ushort(b) << 16);
}

#define CP16(saddr, gaddr) \
    asm volatile("cp.async.cg.shared.global [%0], [%1], 16;" :: "r"(saddr), "l"(gaddr))
#define CP_COMMIT() asm volatile("cp.async.commit_group;" ::: "memory")
#define CP_WAIT0()  asm volatile("cp.async.wait_group 0;" ::: "memory")

#define LDSM4(r, addr) \
    asm volatile("ldmatrix.sync.aligned.m8n8.x4.shared.b16 {%0,%1,%2,%3}, [%4];" \
        : "=r"((r)[0]), "=r"((r)[1]), "=r"((r)[2]), "=r"((r)[3]) : "r"(addr))

#define MMAH(d, a, b0, b1) \
    asm volatile("mma.sync.aligned.m16n8k16.row.col.f32.f16.f16.f32 " \
        "{%0,%1,%2,%3}, {%4,%5,%6,%7}, {%8,%9}, {%0,%1,%2,%3};" \
        : "+f"((d)[0]), "+f"((d)[1]), "+f"((d)[2]), "+f"((d)[3]) \
        : "r"((a)[0]), "r"((a)[1]), "r"((a)[2]), "r"((a)[3]), "r"(b0), "r"(b1))

// =====================================================================
// K0: zero the partial-o buffer (both slots)
// =====================================================================
__global__ void __launch_bounds__(256) k_zero() {
    const size_t i = (size_t)blockIdx.x * 256 + threadIdx.x;   // < 983040
    reinterpret_cast<float4*>(g_obuf)[i] = make_float4(0.f, 0.f, 0.f, 0.f);
}

// =====================================================================
// K1: per-token LN stats + fp16 conversion of xn (fused)
// =====================================================================
__global__ void __launch_bounds__(256) k_split(const float* __restrict__ x) {
    const int t = blockIdx.x;
    const float4 v = reinterpret_cast<const float4*>(x)[(size_t)t * 256 + threadIdx.x];
    float s = v.x + v.y + v.z + v.w;
    float q = v.x * v.x + v.y * v.y + v.z * v.z + v.w * v.w;
    #pragma unroll
    for (int o = 16; o > 0; o >>= 1) {
        s += __shfl_xor_sync(0xffffffffu, s, o);
        q += __shfl_xor_sync(0xffffffffu, q, o);
    }
    __shared__ float ss[8], qq[8], smu, srs;
    const int w = threadIdx.x >> 5;
    if ((threadIdx.x & 31) == 0) { ss[w] = s; qq[w] = q; }
    __syncthreads();
    if (threadIdx.x == 0) {
        float S = 0.f, Q = 0.f;
        #pragma unroll
        for (int i = 0; i < 8; i++) { S += ss[i]; Q += qq[i]; }
        float mu  = S * (1.0f / (float)NXD);
        float var = fmaxf(Q * (1.0f / (float)NXD) - mu * mu, 0.0f);
        smu = mu;
        srs = 1.0f / sqrtf(var + LN_EPS);
    }
    __syncthreads();
    const float mu = smu, rs = srs;
    uint2 H;
    H.x = pk2h(__float2half((v.x - mu) * rs), __float2half((v.y - mu) * rs));
    H.y = pk2h(__float2half((v.z - mu) * rs), __float2half((v.w - mu) * rs));
    reinterpret_cast<uint2*>(g_A)[(size_t)t * 256 + threadIdx.x] = H;
}

// =====================================================================
// K2a: B = (ln_g ⊙ W1)^T -> [NPAD][K] fp16 (pad rows zero)
// =====================================================================
__global__ void __launch_bounds__(256) k_prepB(const float* __restrict__ ln_g,
                                               const float* __restrict__ W1) {
    const int n = blockIdx.x;
    int a = 0, h = 0;
    const bool val = (n < NC);
    if (val) { a = n / H_CNT; h = n - a * H_CNT; }
    #pragma unroll
    for (int j = 0; j < 4; j++) {
        const int k = threadIdx.x + j * 256;
        float wv = val ? ln_g[a * NXD + k] * W1[((size_t)a * NXD + k) * H_CNT + h] : 0.0f;
        g_B[(size_t)n * NXD + k] = __float2half(wv);
    }
}

// =====================================================================
// K2b: off[a,h] = ln_b[a,:]·W1[a,:,h] + b1[a,h]
// =====================================================================
__global__ void __launch_bounds__(64) k_off(const float* __restrict__ ln_b,
                                            const float* __restrict__ W1,
                                            const float* __restrict__ b1) {
    const int a = blockIdx.x;
    const int h = threadIdx.x;
    if (h >= H_CNT) return;
    const float* lb = ln_b + a * NXD;
    const float* w  = W1 + (size_t)a * NXD * H_CNT + h;
    float acc = 0.0f;
    #pragma unroll 8
    for (int n = 0; n < NXD; n++) acc += lb[n] * w[(size_t)n * H_CNT];
    g_off[a * H_CNT + h] = acc + b1[a * H_CNT + h];
}

// =====================================================================
// K3: fp16 mma.sync GEMM + FUSED second GEMM epilogue.
//   mainloop: CTA 128x128, BK=64, 4 warps (2x2), warp tile 64x64,
//             cp.async 2-stage (R8 config, best measured).
//   epilogue: h=relu(acc+off) -> fp16 smem tile [128][136];
//             per-thread token GEMV over this chunk's 128 cols with W2,
//             STREAMED one uint4 (4 half2 pairs) at a time (no big array);
//             partial o[t,a,j] -> g_obuf slot (0: adapter starts in this
//             chunk; 1: adapter started in previous chunk). No atomics.
// =====================================================================
#define SSTR   144
#define TILE_B (128 * SSTR)          // 18432
#define STAGE  (2 * TILE_B)          // 36864
#define SMEMT  (2 * STAGE)           // 73728
#define NKT    16
#define HS     136                   // epilogue h-stage stride (halfs)

__global__ void __launch_bounds__(128, 2) k_gemm(const float* __restrict__ W2) {
    extern __shared__ __align__(16) char smem[];
    const uint32_t sb = s2u(smem);
    const int tid = threadIdx.x;
    const int w = tid >> 5, l = tid & 31;
    const int wm = w & 1, wn = w >> 1;          // 2 x 2 warp grid, 64x64 tiles
    const int bx = blockIdx.x;                  // N tile 0..7 (fastest -> A L2 reuse)
    const int by = blockIdx.y;                  // M tile 0..255

    // ---- loader mapping: 8 chunks of 16B per tile per thread (BK=64) ----
    unsigned soff[8], rel[8];
    #pragma unroll
    for (int i = 0; i < 8; i++) {
        unsigned c = tid + i * 128;             // 0..1023
        unsigned row = c >> 3, kq = c & 7;      // 128 rows x 8 u16B
        soff[i] = row * SSTR + kq * 16;
        rel[i]  = row * NXD + kq * 8;
    }
    const char* gA = reinterpret_cast<const char*>(g_A) + (size_t)by * 128 * NXD * 2;
    const char* gB = reinterpret_cast<const char*>(g_B) + (size_t)bx * 128 * NXD * 2;

    auto load_stage = [&](int kt, int s) {
        const uint32_t st = sb + s * STAGE;
        const unsigned kofs = kt * 64;
        #pragma unroll
        for (int i = 0; i < 8; i++) {
            CP16(st + soff[i],          gA + (size_t)(rel[i] + kofs) * 2);
            CP16(st + TILE_B + soff[i], gB + (size_t)(rel[i] + kofs) * 2);
        }
        CP_COMMIT();
    };

    uint32_t abase[4], bbase[4];
    #pragma unroll
    for (int mi = 0; mi < 4; mi++)
        abase[mi] = (wm * 64 + mi * 16 + (l & 15)) * SSTR + (l >> 4) * 16;
    #pragma unroll
    for (int pi = 0; pi < 4; pi++)
        bbase[pi] = (wn * 64 + pi * 16 + (l & 15)) * SSTR + (l >> 4) * 16;

    float acc[4][8][4];
    #pragma unroll
    for (int mi = 0; mi < 4; mi++)
        #pragma unroll
        for (int ni = 0; ni < 8; ni++)
            #pragma unroll
            for (int r = 0; r < 4; r++) acc[mi][ni][r] = 0.0f;

    load_stage(0, 0);

    for (int kt = 0; kt < NKT; kt++) {
        const int s = kt & 1;
        CP_WAIT0();
        __syncthreads();
        if (kt < NKT - 1) load_stage(kt + 1, s ^ 1);

        const uint32_t stA = sb + s * STAGE;
        const uint32_t stB = stA + TILE_B;
        #pragma unroll
        for (int ks = 0; ks < 4; ks++) {
            const uint32_t ko = ks * 32;
            uint32_t a_[4][4], b_[4][4];
            #pragma unroll
            for (int mi = 0; mi < 4; mi++) LDSM4(a_[mi], stA + abase[mi] + ko);
            #pragma unroll
            for (int pi = 0; pi < 4; pi++) LDSM4(b_[pi], stB + bbase[pi] + ko);
            #pragma unroll
            for (int mi = 0; mi < 4; mi++)
                #pragma unroll
                for (int ni = 0; ni < 8; ni++) {
                    const int pi = ni >> 1, sel = ni & 1;
                    MMAH(acc[mi][ni], a_[mi], b_[pi][sel], b_[pi][sel + 2]);
                }
        }
        __syncthreads();
    }

    // ================= fused epilogue =================
    // adapter span of this 128-col chunk
    const int col0 = bx * 128;
    const int a0   = col0 / H_CNT;
    const int lastc = (col0 + 127 < NC) ? (col0 + 127) : (NC - 1);
    const int a1v  = lastc / H_CNT;

    __half* hst = reinterpret_cast<__half*>(smem);                  // [128][HS] halfs
    float*  W2s = reinterpret_cast<float*>(smem + 128 * HS * 2);    // <= 600 floats

    // cooperative W2 slice load (region disjoint from hst)
    const int nW = (a1v - a0 + 1) * H_CNT * O_CNT;
    for (int i = tid; i < nW; i += 128)
        W2s[i] = W2[a0 * H_CNT * O_CNT + i];

    // stage h = relu(acc + off) as fp16
    const int cb0 = col0 + wn * 64 + (l & 3) * 2;                   // global col (even)
    #pragma unroll
    for (int mi = 0; mi < 4; mi++) {
        const int lr = wm * 64 + (l >> 2) + mi * 16;
        #pragma unroll
        for (int ni = 0; ni < 8; ni++) {
            const int gc = cb0 + ni * 8;
            const int lc = wn * 64 + (l & 3) * 2 + ni * 8;
            float o0 = 0.0f, o1 = 0.0f;
            if (gc < NC) { o0 = g_off[gc]; o1 = g_off[gc + 1]; }
            __half2 v0 = __floats2half2_rn(fmaxf(acc[mi][ni][0] + o0, 0.0f),
                                           fmaxf(acc[mi][ni][1] + o1, 0.0f));
            __half2 v1 = __floats2half2_rn(fmaxf(acc[mi][ni][2] + o0, 0.0f),
                                           fmaxf(acc[mi][ni][3] + o1, 0.0f));
            *reinterpret_cast<__half2*>(hst + lr * HS + lc)       = v0;
            *reinterpret_cast<__half2*>(hst + (lr + 8) * HS + lc) = v1;
        }
    }
    __syncthreads();

    // per-thread token GEMV, streamed (one uint4 = 8 halfs = 4 pairs at a time)
    const int tok = tid;                        // 0..127 row in tile
    const uint4* hrow4 = reinterpret_cast<const uint4*>(
        reinterpret_cast<const char*>(hst) + tok * (HS * 2));

    float o_loc[12];
    #pragma unroll
    for (int i = 0; i < 12; i++) o_loc[i] = 0.0f;

    const int nu4 = ((lastc + 1) - col0) / 8;   // chunk length always /8 (128 or 104)
    int hc = col0 - a0 * H_CNT;                 // even
    int ai = 0;
    for (int i = 0; i < nu4; i++) {
        const uint4 v = hrow4[i];
        uint32_t pr[4] = {v.x, v.y, v.z, v.w};
        #pragma unroll
        for (int p = 0; p < 4; p++) {
            float2 f = __half22float2(*reinterpret_cast<const __half2*>(&pr[p]));
            const float* wv = &W2s[ai * (H_CNT * O_CNT) + hc * O_CNT];
            o_loc[ai * 3 + 0] += f.x * wv[0] + f.y * wv[3];
            o_loc[ai * 3 + 1] += f.x * wv[1] + f.y * wv[4];
            o_loc[ai * 3 + 2] += f.x * wv[2] + f.y * wv[5];
            hc += 2;
            if (hc == H_CNT) { hc = 0; ai++; }
        }
    }

    const int tg = by * 128 + tok;
    #pragma unroll
    for (int q = 0; q < 4; q++) {
        const int a = a0 + q;
        if (a > a1v) break;
        const int slot = (q == 0 && a0 * H_CNT < col0) ? 1 : 0;
        float* dst = g_obuf[slot] + (size_t)tg * 60 + a * 3;
        dst[0] = o_loc[q * 3 + 0];
        dst[1] = o_loc[q * 3 + 1];
        dst[2] = o_loc[q * 3 + 2];
    }
}

// =====================================================================
// K4: sum partial o slots + b2, cross-adapter squash, write output
// =====================================================================
__global__ void __launch_bounds__(256) k_sq(const float* __restrict__ b2,
                                            float* __restrict__ out) {
    __shared__ float osm[8][64];
    __shared__ float scl[8][4];
    const int tid = threadIdx.x;
    const int w = tid >> 5, l = tid & 31;
    const int t = blockIdx.x * 8 + w;
    const float* o0 = g_obuf[0] + (size_t)t * 60;
    const float* o1 = g_obuf[1] + (size_t)t * 60;

    #pragma unroll
    for (int r = 0; r < 2; r++) {
        const int p = l + r * 32;
        if (p < A_CNT * O_CNT) osm[w][p] = o0[p] + o1[p] + b2[p];
    }
    __syncwarp();

    if (l < O_CNT) {
        float sq = 0.0f;
        #pragma unroll
        for (int a = 0; a < A_CNT; a++) { float v = osm[w][a * 3 + l]; sq += v * v; }
        scl[w][l] = sqrtf(sq) / (1.0f + sq);
    }
    __syncwarp();

    const int b = t >> 11, sidx = t & (S_LEN - 1);
    #pragma unroll
    for (int r = 0; r < 2; r++) {
        const int p = l + r * 32;
        if (p < A_CNT * O_CNT) {
            const int a = p / 3, j = p - a * 3;
            out[(size_t)(b * A_CNT + a) * (S_LEN * O_CNT) + sidx * 3 + j] =
                osm[w][p] * scl[w][j];
        }
    }
}

// =====================================================================
// launch
// =====================================================================
extern "C" void kernel_launch(void* const* d_in, const int* in_sizes, int n_in,
                              void* d_out, int out_size) {
    (void)in_sizes; (void)n_in; (void)out_size;
    const float* x    = (const float*)d_in[0];
    const float* ln_g = (const float*)d_in[1];
    const float* ln_b = (const float*)d_in[2];
    const float* W1   = (const float*)d_in[3];
    const float* b1   = (const float*)d_in[4];
    const float* W2   = (const float*)d_in[5];
    const float* b2   = (const float*)d_in[6];
    float* out = (float*)d_out;

    cudaFuncSetAttribute(k_gemm, cudaFuncAttributeMaxDynamicSharedMemorySize, SMEMT);

    k_zero<<<(2 * T_TOK * 60 / 4) / 256, 256>>>();
    k_split<<<T_TOK, 256>>>(x);
    k_prepB<<<NPAD, 256>>>(ln_g, W1);
    k_off<<<A_CNT, 64>>>(ln_b, W1, b1);
    k_gemm<<<dim3(8, 256), 128, SMEMT>>>(W2);
    k_sq<<<T_TOK / 8, 256>>>(b2, out);
}

// round 12
// speedup vs baseline: 7.1290x; 1.1631x over previous
#include <cuda_runtime.h>
#include <cuda_fp16.h>
#include <cstdint>

// ---------------- problem constants ----------------
#define T_TOK   32768            // B*S tokens
#define NXD     1024             // feature dim (K)
#define A_CNT   20
#define H_CNT   50
#define O_CNT   3
#define NC      1000             // A_CNT*H_CNT real columns
#define NPAD    1024             // padded N
#define S_LEN   2048
#define LN_EPS  1e-5f
#define KB_OFF  8                // k-chunks for k_off partials

// ---------------- device scratch ----------------
__device__ float g_off[NC];
__device__ float g_offp[A_CNT * KB_OFF * H_CNT];             // k_off partials
__device__ float g_obuf[2][(size_t)T_TOK * 60];              // partial o, 2 slots, 15.7 MB
__device__ __align__(16) __half g_A[(size_t)T_TOK * NXD];    // 64 MB  xn fp16
__device__ __align__(16) __half g_B[(size_t)NPAD * NXD];     // 2 MB   (ln_g*W1)^T fp16

__device__ __forceinline__ uint32_t s2u(const void* p) {
    uint32_t a;
    asm("{ .reg .u64 t; cvta.to.shared.u64 t, %1; cvt.u32.u64 %0, t; }"
        : "=r"(a) : "l"(p));
    return a;
}
__device__ __forceinline__ unsigned pk2h(__half a, __half b) {
    return (unsigned)__half_as_ushort(a) | ((unsigned)__half_as_ushort(b) << 16);
}

#define CP16(saddr, gaddr) \
    asm volatile("cp.async.cg.shared.global [%0], [%1], 16;" :: "r"(saddr), "l"(gaddr))
#define CP_COMMIT() asm volatile("cp.async.commit_group;" ::: "memory")
#define CP_WAIT0()  asm volatile("cp.async.wait_group 0;" ::: "memory")

#define LDSM4(r, addr) \
    asm volatile("ldmatrix.sync.aligned.m8n8.x4.shared.b16 {%0,%1,%2,%3}, [%4];" \
        : "=r"((r)[0]), "=r"((r)[1]), "=r"((r)[2]), "=r"((r)[3]) : "r"(addr))

#define MMAH(d, a, b0, b1) \
    asm volatile("mma.sync.aligned.m16n8k16.row.col.f32.f16.f16.f32 " \
        "{%0,%1,%2,%3}, {%4,%5,%6,%7}, {%8,%9}, {%0,%1,%2,%3};" \
        : "+f"((d)[0]), "+f"((d)[1]), "+f"((d)[2]), "+f"((d)[3]) \
        : "r"((a)[0]), "r"((a)[1]), "r"((a)[2]), "r"((a)[3]), "r"(b0), "r"(b1))

// =====================================================================
// K0: zero the partial-o buffer (both slots)
// =====================================================================
__global__ void __launch_bounds__(256) k_zero() {
    const size_t i = (size_t)blockIdx.x * 256 + threadIdx.x;   // < 983040
    reinterpret_cast<float4*>(g_obuf)[i] = make_float4(0.f, 0.f, 0.f, 0.f);
}

// =====================================================================
// K1: per-token LN stats + fp16 conversion, WARP-PER-TOKEN (no block sync)
//   8 tokens per 256-thread block; lane holds 8 float4s in regs.
// =====================================================================
__global__ void __launch_bounds__(256) k_split(const float* __restrict__ x) {
    const int w = threadIdx.x >> 5, l = threadIdx.x & 31;
    const int t = blockIdx.x * 8 + w;
    const float4* xv = reinterpret_cast<const float4*>(x) + (size_t)t * 256;

    float4 v[8];
    float s = 0.f, q = 0.f;
    #pragma unroll
    for (int j = 0; j < 8; j++) {
        v[j] = xv[l + 32 * j];
        s += v[j].x + v[j].y + v[j].z + v[j].w;
        q += v[j].x * v[j].x + v[j].y * v[j].y + v[j].z * v[j].z + v[j].w * v[j].w;
    }
    #pragma unroll
    for (int o = 16; o > 0; o >>= 1) {
        s += __shfl_xor_sync(0xffffffffu, s, o);
        q += __shfl_xor_sync(0xffffffffu, q, o);
    }
    const float mu  = s * (1.0f / (float)NXD);
    const float var = fmaxf(q * (1.0f / (float)NXD) - mu * mu, 0.0f);
    const float rs  = 1.0f / sqrtf(var + LN_EPS);

    uint2* dst = reinterpret_cast<uint2*>(g_A) + (size_t)t * 256;
    #pragma unroll
    for (int j = 0; j < 8; j++) {
        uint2 H;
        H.x = pk2h(__float2half((v[j].x - mu) * rs), __float2half((v[j].y - mu) * rs));
        H.y = pk2h(__float2half((v[j].z - mu) * rs), __float2half((v[j].w - mu) * rs));
        dst[l + 32 * j] = H;
    }
}

// =====================================================================
// K2a: B = (ln_g ⊙ W1)^T -> [NPAD][K] fp16 (pad rows zero)
// =====================================================================
__global__ void __launch_bounds__(256) k_prepB(const float* __restrict__ ln_g,
                                               const float* __restrict__ W1) {
    const int n = blockIdx.x;
    int a = 0, h = 0;
    const bool val = (n < NC);
    if (val) { a = n / H_CNT; h = n - a * H_CNT; }
    #pragma unroll
    for (int j = 0; j < 4; j++) {
        const int k = threadIdx.x + j * 256;
        float wv = val ? ln_g[a * NXD + k] * W1[((size_t)a * NXD + k) * H_CNT + h] : 0.0f;
        g_B[(size_t)n * NXD + k] = __float2half(wv);
    }
}

// =====================================================================
// K2b stage 1: partial off sums, grid (A_CNT, KB_OFF), coalesced rows
//   thread (g = tid/50, h = tid%50), g in 0..4; sums 128/5 rows.
// =====================================================================
__global__ void __launch_bounds__(256) k_off1(const float* __restrict__ ln_b,
                                              const float* __restrict__ W1) {
    __shared__ float red[5][H_CNT];
    const int a  = blockIdx.x;
    const int kb = blockIdx.y;
    const int tid = threadIdx.x;
    const int g = tid / H_CNT, h = tid - g * H_CNT;   // g<5 active (tid<250)
    float acc = 0.0f;
    if (g < 5) {
        const int n0 = kb * 128;
        for (int r = g; r < 128; r += 5) {
            const int n = n0 + r;
            acc += ln_b[a * NXD + n] * W1[((size_t)a * NXD + n) * H_CNT + h];
        }
        red[g][h] = acc;
    }
    __syncthreads();
    if (tid < H_CNT) {
        float s = red[0][tid] + red[1][tid] + red[2][tid] + red[3][tid] + red[4][tid];
        g_offp[(a * KB_OFF + kb) * H_CNT + tid] = s;
    }
}

// =====================================================================
// K2b stage 2: reduce partials + b1 -> g_off
// =====================================================================
__global__ void __launch_bounds__(256) k_off2(const float* __restrict__ b1) {
    const int p = blockIdx.x * 256 + threadIdx.x;
    if (p >= NC) return;
    const int a = p / H_CNT, h = p - a * H_CNT;
    float s = 0.0f;
    #pragma unroll
    for (int kb = 0; kb < KB_OFF; kb++)
        s += g_offp[(a * KB_OFF + kb) * H_CNT + h];
    g_off[p] = s + b1[p];
}

// =====================================================================
// K3: fp16 mma.sync GEMM + FUSED second GEMM epilogue (unchanged, R11)
// =====================================================================
#define SSTR   144
#define TILE_B (128 * SSTR)          // 18432
#define STAGE  (2 * TILE_B)          // 36864
#define SMEMT  (2 * STAGE)           // 73728
#define NKT    16
#define HS     136                   // epilogue h-stage stride (halfs)

__global__ void __launch_bounds__(128, 2) k_gemm(const float* __restrict__ W2) {
    extern __shared__ __align__(16) char smem[];
    const uint32_t sb = s2u(smem);
    const int tid = threadIdx.x;
    const int w = tid >> 5, l = tid & 31;
    const int wm = w & 1, wn = w >> 1;          // 2 x 2 warp grid, 64x64 tiles
    const int bx = blockIdx.x;                  // N tile 0..7 (fastest -> A L2 reuse)
    const int by = blockIdx.y;                  // M tile 0..255

    unsigned soff[8], rel[8];
    #pragma unroll
    for (int i = 0; i < 8; i++) {
        unsigned c = tid + i * 128;
        unsigned row = c >> 3, kq = c & 7;
        soff[i] = row * SSTR + kq * 16;
        rel[i]  = row * NXD + kq * 8;
    }
    const char* gA = reinterpret_cast<const char*>(g_A) + (size_t)by * 128 * NXD * 2;
    const char* gB = reinterpret_cast<const char*>(g_B) + (size_t)bx * 128 * NXD * 2;

    auto load_stage = [&](int kt, int s) {
        const uint32_t st = sb + s * STAGE;
        const unsigned kofs = kt * 64;
        #pragma unroll
        for (int i = 0; i < 8; i++) {
            CP16(st + soff[i],          gA + (size_t)(rel[i] + kofs) * 2);
            CP16(st + TILE_B + soff[i], gB + (size_t)(rel[i] + kofs) * 2);
        }
        CP_COMMIT();
    };

    uint32_t abase[4], bbase[4];
    #pragma unroll
    for (int mi = 0; mi < 4; mi++)
        abase[mi] = (wm * 64 + mi * 16 + (l & 15)) * SSTR + (l >> 4) * 16;
    #pragma unroll
    for (int pi = 0; pi < 4; pi++)
        bbase[pi] = (wn * 64 + pi * 16 + (l & 15)) * SSTR + (l >> 4) * 16;

    float acc[4][8][4];
    #pragma unroll
    for (int mi = 0; mi < 4; mi++)
        #pragma unroll
        for (int ni = 0; ni < 8; ni++)
            #pragma unroll
            for (int r = 0; r < 4; r++) acc[mi][ni][r] = 0.0f;

    load_stage(0, 0);

    for (int kt = 0; kt < NKT; kt++) {
        const int s = kt & 1;
        CP_WAIT0();
        __syncthreads();
        if (kt < NKT - 1) load_stage(kt + 1, s ^ 1);

        const uint32_t stA = sb + s * STAGE;
        const uint32_t stB = stA + TILE_B;
        #pragma unroll
        for (int ks = 0; ks < 4; ks++) {
            const uint32_t ko = ks * 32;
            uint32_t a_[4][4], b_[4][4];
            #pragma unroll
            for (int mi = 0; mi < 4; mi++) LDSM4(a_[mi], stA + abase[mi] + ko);
            #pragma unroll
            for (int pi = 0; pi < 4; pi++) LDSM4(b_[pi], stB + bbase[pi] + ko);
            #pragma unroll
            for (int mi = 0; mi < 4; mi++)
                #pragma unroll
                for (int ni = 0; ni < 8; ni++) {
                    const int pi = ni >> 1, sel = ni & 1;
                    MMAH(acc[mi][ni], a_[mi], b_[pi][sel], b_[pi][sel + 2]);
                }
        }
        __syncthreads();
    }

    // ================= fused epilogue =================
    const int col0 = bx * 128;
    const int a0   = col0 / H_CNT;
    const int lastc = (col0 + 127 < NC) ? (col0 + 127) : (NC - 1);
    const int a1v  = lastc / H_CNT;

    __half* hst = reinterpret_cast<__half*>(smem);                  // [128][HS] halfs
    float*  W2s = reinterpret_cast<float*>(smem + 128 * HS * 2);    // <= 600 floats

    const int nW = (a1v - a0 + 1) * H_CNT * O_CNT;
    for (int i = tid; i < nW; i += 128)
        W2s[i] = W2[a0 * H_CNT * O_CNT + i];

    const int cb0 = col0 + wn * 64 + (l & 3) * 2;
    #pragma unroll
    for (int mi = 0; mi < 4; mi++) {
        const int lr = wm * 64 + (l >> 2) + mi * 16;
        #pragma unroll
        for (int ni = 0; ni < 8; ni++) {
            const int gc = cb0 + ni * 8;
            const int lc = wn * 64 + (l & 3) * 2 + ni * 8;
            float o0 = 0.0f, o1 = 0.0f;
            if (gc < NC) { o0 = g_off[gc]; o1 = g_off[gc + 1]; }
            __half2 v0 = __floats2half2_rn(fmaxf(acc[mi][ni][0] + o0, 0.0f),
                                           fmaxf(acc[mi][ni][1] + o1, 0.0f));
            __half2 v1 = __floats2half2_rn(fmaxf(acc[mi][ni][2] + o0, 0.0f),
                                           fmaxf(acc[mi][ni][3] + o1, 0.0f));
            *reinterpret_cast<__half2*>(hst + lr * HS + lc)       = v0;
            *reinterpret_cast<__half2*>(hst + (lr + 8) * HS + lc) = v1;
        }
    }
    __syncthreads();

    const int tok = tid;
    const uint4* hrow4 = reinterpret_cast<const uint4*>(
        reinterpret_cast<const char*>(hst) + tok * (HS * 2));

    float o_loc[12];
    #pragma unroll
    for (int i = 0; i < 12; i++) o_loc[i] = 0.0f;

    const int nu4 = ((lastc + 1) - col0) / 8;
    int hc = col0 - a0 * H_CNT;
    int ai = 0;
    for (int i = 0; i < nu4; i++) {
        const uint4 v = hrow4[i];
        uint32_t pr[4] = {v.x, v.y, v.z, v.w};
        #pragma unroll
        for (int p = 0; p < 4; p++) {
            float2 f = __half22float2(*reinterpret_cast<const __half2*>(&pr[p]));
            const float* wv = &W2s[ai * (H_CNT * O_CNT) + hc * O_CNT];
            o_loc[ai * 3 + 0] += f.x * wv[0] + f.y * wv[3];
            o_loc[ai * 3 + 1] += f.x * wv[1] + f.y * wv[4];
            o_loc[ai * 3 + 2] += f.x * wv[2] + f.y * wv[5];
            hc += 2;
            if (hc == H_CNT) { hc = 0; ai++; }
        }
    }

    const int tg = by * 128 + tok;
    #pragma unroll
    for (int q = 0; q < 4; q++) {
        const int a = a0 + q;
        if (a > a1v) break;
        const int slot = (q == 0 && a0 * H_CNT < col0) ? 1 : 0;
        float* dst = g_obuf[slot] + (size_t)tg * 60 + a * 3;
        dst[0] = o_loc[q * 3 + 0];
        dst[1] = o_loc[q * 3 + 1];
        dst[2] = o_loc[q * 3 + 2];
    }
}

// =====================================================================
// K4: sum partial o slots + b2, cross-adapter squash, write output
// =====================================================================
__global__ void __launch_bounds__(256) k_sq(const float* __restrict__ b2,
                                            float* __restrict__ out) {
    __shared__ float osm[8][64];
    __shared__ float scl[8][4];
    const int tid = threadIdx.x;
    const int w = tid >> 5, l = tid & 31;
    const int t = blockIdx.x * 8 + w;
    const float* o0 = g_obuf[0] + (size_t)t * 60;
    const float* o1 = g_obuf[1] + (size_t)t * 60;

    #pragma unroll
    for (int r = 0; r < 2; r++) {
        const int p = l + r * 32;
        if (p < A_CNT * O_CNT) osm[w][p] = o0[p] + o1[p] + b2[p];
    }
    __syncwarp();

    if (l < O_CNT) {
        float sq = 0.0f;
        #pragma unroll
        for (int a = 0; a < A_CNT; a++) { float v = osm[w][a * 3 + l]; sq += v * v; }
        scl[w][l] = sqrtf(sq) / (1.0f + sq);
    }
    __syncwarp();

    const int b = t >> 11, sidx = t & (S_LEN - 1);
    #pragma unroll
    for (int r = 0; r < 2; r++) {
        const int p = l + r * 32;
        if (p < A_CNT * O_CNT) {
            const int a = p / 3, j = p - a * 3;
            out[(size_t)(b * A_CNT + a) * (S_LEN * O_CNT) + sidx * 3 + j] =
                osm[w][p] * scl[w][j];
        }
    }
}

// =====================================================================
// launch
// =====================================================================
extern "C" void kernel_launch(void* const* d_in, const int* in_sizes, int n_in,
                              void* d_out, int out_size) {
    (void)in_sizes; (void)n_in; (void)out_size;
    const float* x    = (const float*)d_in[0];
    const float* ln_g = (const float*)d_in[1];
    const float* ln_b = (const float*)d_in[2];
    const float* W1   = (const float*)d_in[3];
    const float* b1   = (const float*)d_in[4];
    const float* W2   = (const float*)d_in[5];
    const float* b2   = (const float*)d_in[6];
    float* out = (float*)d_out;

    cudaFuncSetAttribute(k_gemm, cudaFuncAttributeMaxDynamicSharedMemorySize, SMEMT);

    k_zero<<<(2 * T_TOK * 60 / 4) / 256, 256>>>();
    k_split<<<T_TOK / 8, 256>>>(x);
    k_prepB<<<NPAD, 256>>>(ln_g, W1);
    k_off1<<<dim3(A_CNT, KB_OFF), 256>>>(ln_b, W1);
    k_off2<<<4, 256>>>(b1);
    k_gemm<<<dim3(8, 256), 128, SMEMT>>>(W2);
    k_sq<<<T_TOK / 8, 256>>>(b2, out);
}

// round 13
// speedup vs baseline: 7.6238x; 1.0694x over previous
#include <cuda_runtime.h>
#include <cuda_fp16.h>
#include <cstdint>

// ---------------- problem constants ----------------
#define T_TOK   32768            // B*S tokens
#define NXD     1024             // feature dim (K)
#define A_CNT   20
#define H_CNT   50
#define O_CNT   3
#define NC      1000             // A_CNT*H_CNT real columns
#define NPAD    1024             // padded N
#define S_LEN   2048
#define LN_EPS  1e-5f
#define KB_OFF  8                // k-chunks for k_off partials

// fused-pre grid ranges
#define NB_SPLIT (T_TOK / 8)                 // 4096
#define NB_PREPB NPAD                        // 1024
#define NB_OFF1  (A_CNT * KB_OFF)            // 160
#define NB_PRE   (NB_SPLIT + NB_PREPB + NB_OFF1)

// ---------------- device scratch ----------------
__device__ float g_off[NC];
__device__ float g_offp[A_CNT * KB_OFF * H_CNT];             // k_off partials
__device__ float g_obuf[2][(size_t)T_TOK * 60];              // partial o, 2 slots
__device__ __align__(16) __half g_A[(size_t)T_TOK * NXD];    // 64 MB  xn fp16
__device__ __align__(16) __half g_B[(size_t)NPAD * NXD];     // 2 MB   (ln_g*W1)^T fp16

__device__ __forceinline__ uint32_t s2u(const void* p) {
    uint32_t a;
    asm("{ .reg .u64 t; cvta.to.shared.u64 t, %1; cvt.u32.u64 %0, t; }"
        : "=r"(a) : "l"(p));
    return a;
}
__device__ __forceinline__ unsigned pk2h(__half a, __half b) {
    return (unsigned)__half_as_ushort(a) | ((unsigned)__half_as_ushort(b) << 16);
}

#define CP16(saddr, gaddr) \
    asm volatile("cp.async.cg.shared.global [%0], [%1], 16;" :: "r"(saddr), "l"(gaddr))
#define CP_COMMIT() asm volatile("cp.async.commit_group;" ::: "memory")
#define CP_WAIT0()  asm volatile("cp.async.wait_group 0;" ::: "memory")

#define LDSM4(r, addr) \
    asm volatile("ldmatrix.sync.aligned.m8n8.x4.shared.b16 {%0,%1,%2,%3}, [%4];" \
        : "=r"((r)[0]), "=r"((r)[1]), "=r"((r)[2]), "=r"((r)[3]) : "r"(addr))

#define MMAH(d, a, b0, b1) \
    asm volatile("mma.sync.aligned.m16n8k16.row.col.f32.f16.f16.f32 " \
        "{%0,%1,%2,%3}, {%4,%5,%6,%7}, {%8,%9}, {%0,%1,%2,%3};" \
        : "+f"((d)[0]), "+f"((d)[1]), "+f"((d)[2]), "+f"((d)[3]) \
        : "r"((a)[0]), "r"((a)[1]), "r"((a)[2]), "r"((a)[3]), "r"(b0), "r"(b1))

// =====================================================================
// K1 (fused pre): blockIdx ranges do LN-split | prepB | off1 concurrently
// =====================================================================
__global__ void __launch_bounds__(256) k_pre(const float* __restrict__ x,
                                             const float* __restrict__ ln_g,
                                             const float* __restrict__ ln_b,
                                             const float* __restrict__ W1) {
    const int blk = blockIdx.x;

    if (blk < NB_SPLIT) {
        // ---- LN stats + fp16 convert, warp-per-token ----
        const int w = threadIdx.x >> 5, l = threadIdx.x & 31;
        const int t = blk * 8 + w;
        const float4* xv = reinterpret_cast<const float4*>(x) + (size_t)t * 256;
        float4 v[8];
        float s = 0.f, q = 0.f;
        #pragma unroll
        for (int j = 0; j < 8; j++) {
            v[j] = xv[l + 32 * j];
            s += v[j].x + v[j].y + v[j].z + v[j].w;
            q += v[j].x * v[j].x + v[j].y * v[j].y + v[j].z * v[j].z + v[j].w * v[j].w;
        }
        #pragma unroll
        for (int o = 16; o > 0; o >>= 1) {
            s += __shfl_xor_sync(0xffffffffu, s, o);
            q += __shfl_xor_sync(0xffffffffu, q, o);
        }
        const float mu  = s * (1.0f / (float)NXD);
        const float var = fmaxf(q * (1.0f / (float)NXD) - mu * mu, 0.0f);
        const float rs  = 1.0f / sqrtf(var + LN_EPS);
        uint2* dst = reinterpret_cast<uint2*>(g_A) + (size_t)t * 256;
        #pragma unroll
        for (int j = 0; j < 8; j++) {
            uint2 H;
            H.x = pk2h(__float2half((v[j].x - mu) * rs), __float2half((v[j].y - mu) * rs));
            H.y = pk2h(__float2half((v[j].z - mu) * rs), __float2half((v[j].w - mu) * rs));
            dst[l + 32 * j] = H;
        }
    } else if (blk < NB_SPLIT + NB_PREPB) {
        // ---- prepB: B = (ln_g ⊙ W1)^T fp16 (pad rows zero) ----
        const int n = blk - NB_SPLIT;
        int a = 0, h = 0;
        const bool val = (n < NC);
        if (val) { a = n / H_CNT; h = n - a * H_CNT; }
        #pragma unroll
        for (int j = 0; j < 4; j++) {
            const int k = threadIdx.x + j * 256;
            float wv = val ? ln_g[a * NXD + k] * W1[((size_t)a * NXD + k) * H_CNT + h] : 0.0f;
            g_B[(size_t)n * NXD + k] = __float2half(wv);
        }
    } else {
        // ---- off1: partial beta-fold sums ----
        __shared__ float red[5][H_CNT];
        const int idx = blk - NB_SPLIT - NB_PREPB;
        const int a  = idx / KB_OFF;
        const int kb = idx - a * KB_OFF;
        const int tid = threadIdx.x;
        const int g = tid / H_CNT, h = tid - g * H_CNT;
        float acc = 0.0f;
        if (g < 5) {
            const int n0 = kb * 128;
            for (int r = g; r < 128; r += 5) {
                const int n = n0 + r;
                acc += ln_b[a * NXD + n] * W1[((size_t)a * NXD + n) * H_CNT + h];
            }
            red[g][h] = acc;
        }
        __syncthreads();
        if (tid < H_CNT) {
            float sv = red[0][tid] + red[1][tid] + red[2][tid] + red[3][tid] + red[4][tid];
            g_offp[(a * KB_OFF + kb) * H_CNT + tid] = sv;
        }
    }
}

// =====================================================================
// K2: reduce off partials + b1 -> g_off
// =====================================================================
__global__ void __launch_bounds__(256) k_off2(const float* __restrict__ b1) {
    const int p = blockIdx.x * 256 + threadIdx.x;
    if (p >= NC) return;
    const int a = p / H_CNT, h = p - a * H_CNT;
    float s = 0.0f;
    #pragma unroll
    for (int kb = 0; kb < KB_OFF; kb++)
        s += g_offp[(a * KB_OFF + kb) * H_CNT + h];
    g_off[p] = s + b1[p];
}

// =====================================================================
// K3: fp16 mma.sync GEMM + fused second-GEMM epilogue
//   CTA 128x128, BK=64, 8 warps (2Mx4N), warp tile 64x32,
//   cp.async 2-stage, 2 CTAs/SM => 16 warps/SM (4/SMSP).
// =====================================================================
#define SSTR   144
#define TILE_B (128 * SSTR)          // 18432
#define STAGE  (2 * TILE_B)          // 36864
#define SMEMT  (2 * STAGE)           // 73728
#define NKT    16
#define HS     136                   // epilogue h-stage stride (halfs)

__global__ void __launch_bounds__(256, 2) k_gemm(const float* __restrict__ W2) {
    extern __shared__ __align__(16) char smem[];
    const uint32_t sb = s2u(smem);
    const int tid = threadIdx.x;
    const int w = tid >> 5, l = tid & 31;
    const int wm = w & 1, wn = w >> 1;          // 2(M) x 4(N), warp tile 64x32
    const int bx = blockIdx.x;                  // N tile 0..7
    const int by = blockIdx.y;                  // M tile 0..255

    // ---- loader mapping: 4 chunks of 16B per tile per thread ----
    unsigned soff[4], rel[4];
    #pragma unroll
    for (int i = 0; i < 4; i++) {
        unsigned c = tid + i * 256;             // 0..1023
        unsigned row = c >> 3, kq = c & 7;
        soff[i] = row * SSTR + kq * 16;
        rel[i]  = row * NXD + kq * 8;
    }
    const char* gA = reinterpret_cast<const char*>(g_A) + (size_t)by * 128 * NXD * 2;
    const char* gB = reinterpret_cast<const char*>(g_B) + (size_t)bx * 128 * NXD * 2;

    auto load_stage = [&](int kt, int s) {
        const uint32_t st = sb + s * STAGE;
        const unsigned kofs = kt * 64;
        #pragma unroll
        for (int i = 0; i < 4; i++) {
            CP16(st + soff[i],          gA + (size_t)(rel[i] + kofs) * 2);
            CP16(st + TILE_B + soff[i], gB + (size_t)(rel[i] + kofs) * 2);
        }
        CP_COMMIT();
    };

    uint32_t abase[4], bbase[2];
    #pragma unroll
    for (int mi = 0; mi < 4; mi++)
        abase[mi] = (wm * 64 + mi * 16 + (l & 15)) * SSTR + (l >> 4) * 16;
    #pragma unroll
    for (int pi = 0; pi < 2; pi++)
        bbase[pi] = (wn * 32 + pi * 16 + (l & 15)) * SSTR + (l >> 4) * 16;

    float acc[4][4][4];
    #pragma unroll
    for (int mi = 0; mi < 4; mi++)
        #pragma unroll
        for (int ni = 0; ni < 4; ni++)
            #pragma unroll
            for (int r = 0; r < 4; r++) acc[mi][ni][r] = 0.0f;

    load_stage(0, 0);

    for (int kt = 0; kt < NKT; kt++) {
        const int s = kt & 1;
        CP_WAIT0();
        __syncthreads();
        if (kt < NKT - 1) load_stage(kt + 1, s ^ 1);

        const uint32_t stA = sb + s * STAGE;
        const uint32_t stB = stA + TILE_B;
        #pragma unroll
        for (int ks = 0; ks < 4; ks++) {
            const uint32_t ko = ks * 32;
            uint32_t a_[4][4], b_[2][4];
            #pragma unroll
            for (int mi = 0; mi < 4; mi++) LDSM4(a_[mi], stA + abase[mi] + ko);
            #pragma unroll
            for (int pi = 0; pi < 2; pi++) LDSM4(b_[pi], stB + bbase[pi] + ko);
            #pragma unroll
            for (int mi = 0; mi < 4; mi++)
                #pragma unroll
                for (int ni = 0; ni < 4; ni++) {
                    const int pi = ni >> 1, sel = ni & 1;
                    MMAH(acc[mi][ni], a_[mi], b_[pi][sel], b_[pi][sel + 2]);
                }
        }
        __syncthreads();
    }

    // ================= fused epilogue =================
    const int col0 = bx * 128;
    const int a0   = col0 / H_CNT;
    const int lastc = (col0 + 127 < NC) ? (col0 + 127) : (NC - 1);
    const int a1v  = lastc / H_CNT;

    __half* hst = reinterpret_cast<__half*>(smem);                  // [128][HS] halfs
    float*  W2s = reinterpret_cast<float*>(smem + 128 * HS * 2);

    const int nW = (a1v - a0 + 1) * H_CNT * O_CNT;
    for (int i = tid; i < nW; i += 256)
        W2s[i] = W2[a0 * H_CNT * O_CNT + i];

    // stage h = relu(acc + off) as fp16 (warp tile 64x32 mapping)
    #pragma unroll
    for (int mi = 0; mi < 4; mi++) {
        const int lr = wm * 64 + mi * 16 + (l >> 2);
        #pragma unroll
        for (int ni = 0; ni < 4; ni++) {
            const int lc = wn * 32 + ni * 8 + (l & 3) * 2;
            const int gc = col0 + lc;
            float o0 = 0.0f, o1 = 0.0f;
            if (gc < NC) { o0 = g_off[gc]; o1 = g_off[gc + 1]; }
            __half2 v0 = __floats2half2_rn(fmaxf(acc[mi][ni][0] + o0, 0.0f),
                                           fmaxf(acc[mi][ni][1] + o1, 0.0f));
            __half2 v1 = __floats2half2_rn(fmaxf(acc[mi][ni][2] + o0, 0.0f),
                                           fmaxf(acc[mi][ni][3] + o1, 0.0f));
            *reinterpret_cast<__half2*>(hst + lr * HS + lc)       = v0;
            *reinterpret_cast<__half2*>(hst + (lr + 8) * HS + lc) = v1;
        }
    }
    __syncthreads();

    // per-thread token GEMV (threads 0..127), streamed uint4
    if (tid < 128) {
        const int tok = tid;
        const uint4* hrow4 = reinterpret_cast<const uint4*>(
            reinterpret_cast<const char*>(hst) + tok * (HS * 2));

        float o_loc[12];
        #pragma unroll
        for (int i = 0; i < 12; i++) o_loc[i] = 0.0f;

        const int nu4 = ((lastc + 1) - col0) / 8;
        int hc = col0 - a0 * H_CNT;
        int ai = 0;
        for (int i = 0; i < nu4; i++) {
            const uint4 v = hrow4[i];
            uint32_t pr[4] = {v.x, v.y, v.z, v.w};
            #pragma unroll
            for (int p = 0; p < 4; p++) {
                float2 f = __half22float2(*reinterpret_cast<const __half2*>(&pr[p]));
                const float* wv = &W2s[ai * (H_CNT * O_CNT) + hc * O_CNT];
                o_loc[ai * 3 + 0] += f.x * wv[0] + f.y * wv[3];
                o_loc[ai * 3 + 1] += f.x * wv[1] + f.y * wv[4];
                o_loc[ai * 3 + 2] += f.x * wv[2] + f.y * wv[5];
                hc += 2;
                if (hc == H_CNT) { hc = 0; ai++; }
            }
        }

        const int tg = by * 128 + tok;
        #pragma unroll
        for (int q = 0; q < 4; q++) {
            const int a = a0 + q;
            if (a > a1v) break;
            const int slot = (q == 0 && a0 * H_CNT < col0) ? 1 : 0;
            float* dst = g_obuf[slot] + (size_t)tg * 60 + a * 3;
            dst[0] = o_loc[q * 3 + 0];
            dst[1] = o_loc[q * 3 + 1];
            dst[2] = o_loc[q * 3 + 2];
        }
    }
}

// =====================================================================
// K4: combine slots (slot1 only for chunk-split adapters) + squash
// =====================================================================
__global__ void __launch_bounds__(256) k_sq(const float* __restrict__ b2,
                                            float* __restrict__ out) {
    __shared__ float osm[8][64];
    __shared__ float scl[8][4];
    const int tid = threadIdx.x;
    const int w = tid >> 5, l = tid & 31;
    const int t = blockIdx.x * 8 + w;
    const float* o0 = g_obuf[0] + (size_t)t * 60;
    const float* o1 = g_obuf[1] + (size_t)t * 60;

    #pragma unroll
    for (int r = 0; r < 2; r++) {
        const int p = l + r * 32;
        if (p < A_CNT * O_CNT) {
            const int a = p / 3;
            const int st = a * H_CNT;
            const bool split = (st >> 7) != ((st + H_CNT - 1) >> 7);
            osm[w][p] = o0[p] + (split ? o1[p] : 0.0f) + b2[p];
        }
    }
    __syncwarp();

    if (l < O_CNT) {
        float sq = 0.0f;
        #pragma unroll
        for (int a = 0; a < A_CNT; a++) { float v = osm[w][a * 3 + l]; sq += v * v; }
        scl[w][l] = sqrtf(sq) / (1.0f + sq);
    }
    __syncwarp();

    const int b = t >> 11, sidx = t & (S_LEN - 1);
    #pragma unroll
    for (int r = 0; r < 2; r++) {
        const int p = l + r * 32;
        if (p < A_CNT * O_CNT) {
            const int a = p / 3, j = p - a * 3;
            out[(size_t)(b * A_CNT + a) * (S_LEN * O_CNT) + sidx * 3 + j] =
                osm[w][p] * scl[w][j];
        }
    }
}

// =====================================================================
// launch
// =====================================================================
extern "C" void kernel_launch(void* const* d_in, const int* in_sizes, int n_in,
                              void* d_out, int out_size) {
    (void)in_sizes; (void)n_in; (void)out_size;
    const float* x    = (const float*)d_in[0];
    const float* ln_g = (const float*)d_in[1];
    const float* ln_b = (const float*)d_in[2];
    const float* W1   = (const float*)d_in[3];
    const float* b1   = (const float*)d_in[4];
    const float* W2   = (const float*)d_in[5];
    const float* b2   = (const float*)d_in[6];
    float* out = (float*)d_out;

    cudaFuncSetAttribute(k_gemm, cudaFuncAttributeMaxDynamicSharedMemorySize, SMEMT);

    k_pre<<<NB_PRE, 256>>>(x, ln_g, ln_b, W1);
    k_off2<<<4, 256>>>(b1);
    k_gemm<<<dim3(8, 256), 256, SMEMT>>>(W2);
    k_sq<<<T_TOK / 8, 256>>>(b2, out);
}